// round 1
// baseline (speedup 1.0000x reference)
#include <cuda_runtime.h>
#include <math.h>

#define BATCH 8
#define DIMC  256
#define HH    48
#define WWD   48
#define HW    2304      // 48*48
#define HEADS 8
#define DH    32
#define HKD   24
#define NKS   576       // 24*24
#define ATTN_SCALE 0.17677669529663687f   // 32^-0.5

// -------------------- scratch (device globals; no allocation) --------------------
__device__ float g_q  [BATCH * DIMC * HW];   // q projection (B,256,2304)
__device__ float g_kvs[BATCH * DIMC * NKS];  // sampled kv   (B,256,576)
__device__ float g_k  [BATCH * DIMC * NKS];
__device__ float g_v  [BATCH * DIMC * NKS];
__device__ float g_ao [BATCH * DIMC * HW];   // attention output (B,256,2304)

// -------------------- warp reduce helpers --------------------
__device__ __forceinline__ float warp_sum(float v) {
#pragma unroll
    for (int o = 16; o; o >>= 1) v += __shfl_xor_sync(0xffffffffu, v, o);
    return v;
}
__device__ __forceinline__ float warp_max(float v) {
#pragma unroll
    for (int o = 16; o; o >>= 1) v = fmaxf(v, __shfl_xor_sync(0xffffffffu, v, o));
    return v;
}

// -------------------- batched GEMM: C[b] = W(256x256) * X[b](256xN) + bias --------------------
// grid: (N/64, 256/64, BATCH), block 256. 4x4 microtile per thread, BK=16.
__global__ void gemm_bias_kernel(const float* __restrict__ W,
                                 const float* __restrict__ X,
                                 const float* __restrict__ bias,
                                 float* __restrict__ C, int N)
{
    __shared__ float As[16][64];
    __shared__ float Bs[16][64];

    const int n0 = blockIdx.x * 64;
    const int m0 = blockIdx.y * 64;
    X += (size_t)blockIdx.z * DIMC * N;
    C += (size_t)blockIdx.z * DIMC * N;

    const int tid = threadIdx.x;
    const int tx = tid & 15, ty = tid >> 4;

    float acc[4][4] = {};

    for (int k0 = 0; k0 < DIMC; k0 += 16) {
        {   // A tile (transposed store): W[(m0+mm), k0+kq*4 .. +3]
            int mm = tid >> 2, kq = tid & 3;
            float4 a = *(const float4*)(W + (size_t)(m0 + mm) * DIMC + k0 + kq * 4);
            As[kq * 4 + 0][mm] = a.x;
            As[kq * 4 + 1][mm] = a.y;
            As[kq * 4 + 2][mm] = a.z;
            As[kq * 4 + 3][mm] = a.w;
        }
        {   // B tile
            int r = tid >> 4, cq = tid & 15;
            *(float4*)(&Bs[r][cq * 4]) =
                *(const float4*)(X + (size_t)(k0 + r) * N + n0 + cq * 4);
        }
        __syncthreads();
#pragma unroll
        for (int kk = 0; kk < 16; ++kk) {
            float4 a = *(const float4*)(&As[kk][ty * 4]);
            float4 b = *(const float4*)(&Bs[kk][tx * 4]);
            float av[4] = {a.x, a.y, a.z, a.w};
            float bv[4] = {b.x, b.y, b.z, b.w};
#pragma unroll
            for (int i = 0; i < 4; ++i)
#pragma unroll
                for (int j = 0; j < 4; ++j) acc[i][j] += av[i] * bv[j];
        }
        __syncthreads();
    }

#pragma unroll
    for (int i = 0; i < 4; ++i) {
        float bi = bias[m0 + ty * 4 + i];
        float4 o = make_float4(acc[i][0] + bi, acc[i][1] + bi,
                               acc[i][2] + bi, acc[i][3] + bi);
        *(float4*)(C + (size_t)(m0 + ty * 4 + i) * N + n0 + tx * 4) = o;
    }
}

// -------------------- depthwise conv + LN + GELU + offset + bilinear sample --------------------
// one warp per output position (bh, hk, wk); lane = channel dh.
// grid: 64*576/8 = 4608 blocks of 256 threads.
__global__ void offset_sample_kernel(const float* __restrict__ q,
                                     const float* __restrict__ kv,
                                     const float* __restrict__ w_dw,
                                     const float* __restrict__ b_dw,
                                     const float* __restrict__ ln_w,
                                     const float* __restrict__ ln_b,
                                     const float* __restrict__ w_off,
                                     float* __restrict__ kvs)
{
    __shared__ float s_wdw[32 * 25];
    __shared__ float s_bdw[32], s_lnw[32], s_lnb[32], s_woff[64];

    const int tid = threadIdx.x;
    for (int i = tid; i < 800; i += 256) s_wdw[i] = w_dw[i];
    if (tid < 32) { s_bdw[tid] = b_dw[tid]; s_lnw[tid] = ln_w[tid]; s_lnb[tid] = ln_b[tid]; }
    if (tid < 64) s_woff[tid] = w_off[tid];
    __syncthreads();

    const int wid  = blockIdx.x * 8 + (tid >> 5);   // 0..36863
    const int lane = tid & 31;

    const int bh  = wid / NKS;
    const int pos = wid - bh * NKS;
    const int hk  = pos / HKD;
    const int wk  = pos - hk * HKD;
    const int b   = bh >> 3;
    const int h   = bh & 7;

    const float* qc = q + ((size_t)(b * DIMC + h * DH + lane)) * HW;

    // depthwise 5x5, stride 2, pad 2
    float t = 0.f;
    const int y0 = hk * 2 - 2, x0 = wk * 2 - 2;
#pragma unroll
    for (int i = 0; i < 5; ++i) {
        int yy = y0 + i;
        if ((unsigned)yy < (unsigned)HH) {
#pragma unroll
            for (int j = 0; j < 5; ++j) {
                int xx = x0 + j;
                if ((unsigned)xx < (unsigned)WWD)
                    t += qc[yy * WWD + xx] * s_wdw[lane * 25 + i * 5 + j];
            }
        }
    }
    t += s_bdw[lane];

    // LayerNorm over 32 channels
    float mu  = warp_sum(t) * (1.f / 32.f);
    float d   = t - mu;
    float var = warp_sum(d * d) * (1.f / 32.f);
    t = d * rsqrtf(var + 1e-5f) * s_lnw[lane] + s_lnb[lane];

    // exact GELU
    t = 0.5f * t * (1.f + erff(t * 0.70710678118654752f));

    // offsets: w_off (2,32)
    float o0 = warp_sum(s_woff[lane] * t);        // y offset
    float o1 = warp_sum(s_woff[32 + lane] * t);   // x offset

    const float refy = (0.5f + (float)hk) * (2.f / 23.f) - 1.f;
    const float refx = (0.5f + (float)wk) * (2.f / 23.f) - 1.f;
    float py = fminf(fmaxf(o0 + refy, -1.f), 1.f);
    float px = fminf(fmaxf(o1 + refx, -1.f), 1.f);

    // bilinear sample from kv (48x48)
    float gx = (px + 1.f) * 0.5f * 47.f;
    float gy = (py + 1.f) * 0.5f * 47.f;
    float fx = floorf(gx), fy = floorf(gy);
    float wx = gx - fx,   wy = gy - fy;
    int x0i = min(max((int)fx, 0), 47);
    int x1i = min(max((int)fx + 1, 0), 47);
    int y0i = min(max((int)fy, 0), 47);
    int y1i = min(max((int)fy + 1, 0), 47);

    const float* kvc = kv + ((size_t)(b * DIMC + h * DH + lane)) * HW;
    float v00 = kvc[y0i * WWD + x0i];
    float v01 = kvc[y0i * WWD + x1i];
    float v10 = kvc[y1i * WWD + x0i];
    float v11 = kvc[y1i * WWD + x1i];

    float val = (1.f - wx) * (1.f - wy) * v00 + wx * (1.f - wy) * v01 +
                (1.f - wx) * wy * v10 + wx * wy * v11;

    kvs[((size_t)(b * DIMC + h * DH + lane)) * NKS + pos] = val;
}

// -------------------- attention: softmax(q^T k * scale) @ v^T per head-batch --------------------
// grid: (4 m-tiles of 576, 64 bh), block 256. K,V tiles resident in smem.
#define KV_PAD 580
#define ATTN_SMEM_FLOATS (2 * 32 * KV_PAD + 8 * 4 * 576)
#define ATTN_SMEM_BYTES  (ATTN_SMEM_FLOATS * 4)

__global__ void attn_kernel(const float* __restrict__ q,
                            const float* __restrict__ k,
                            const float* __restrict__ v,
                            float* __restrict__ out)
{
    extern __shared__ float sm[];
    float* Ksh = sm;                       // [32][580]
    float* Vsh = sm + 32 * KV_PAD;         // [32][580]
    float* Psh = sm + 2 * 32 * KV_PAD;     // [8 warps][4][576]

    const int bh = blockIdx.y;
    const int b  = bh >> 3, h = bh & 7;
    const float* qb = q + (size_t)(b * DIMC + h * DH) * HW;
    const float* kb = k + (size_t)(b * DIMC + h * DH) * NKS;
    const float* vb = v + (size_t)(b * DIMC + h * DH) * NKS;
    float*       ob = out + (size_t)(b * DIMC + h * DH) * HW;

    const int tid = threadIdx.x;
    // cooperative K/V load (float4)
    for (int i = tid; i < 32 * 144; i += 256) {
        int dh = i / 144, c4 = (i - dh * 144) * 4;
        *(float4*)(Ksh + dh * KV_PAD + c4) = *(const float4*)(kb + dh * NKS + c4);
        *(float4*)(Vsh + dh * KV_PAD + c4) = *(const float4*)(vb + dh * NKS + c4);
    }
    __syncthreads();

    const int warp = tid >> 5, lane = tid & 31;
    float* Pw = Psh + warp * 4 * 576;
    const int m0 = blockIdx.x * 576;

    for (int it = 0; it < 18; ++it) {
        const int m = m0 + (it * 8 + warp) * 4;

        float qv[4];
#pragma unroll
        for (int r = 0; r < 4; ++r) qv[r] = qb[(size_t)lane * HW + m + r];

        float s[4][18];
#pragma unroll
        for (int r = 0; r < 4; ++r)
#pragma unroll
            for (int j = 0; j < 18; ++j) s[r][j] = 0.f;

        // scores: s[r][lane + 32j] = sum_dh q[dh][m+r] * K[dh][n]
#pragma unroll 4
        for (int dh = 0; dh < 32; ++dh) {
            const float* Kr = Ksh + dh * KV_PAD + lane;
            float q0 = __shfl_sync(0xffffffffu, qv[0], dh);
            float q1 = __shfl_sync(0xffffffffu, qv[1], dh);
            float q2 = __shfl_sync(0xffffffffu, qv[2], dh);
            float q3 = __shfl_sync(0xffffffffu, qv[3], dh);
#pragma unroll
            for (int j = 0; j < 18; ++j) {
                float kvv = Kr[j * 32];
                s[0][j] += q0 * kvv;
                s[1][j] += q1 * kvv;
                s[2][j] += q2 * kvv;
                s[3][j] += q3 * kvv;
            }
        }

        // softmax per row, write normalized P to smem
#pragma unroll
        for (int r = 0; r < 4; ++r) {
            float mx = -1e30f;
#pragma unroll
            for (int j = 0; j < 18; ++j) mx = fmaxf(mx, s[r][j]);
            mx = warp_max(mx);
            float sum = 0.f;
#pragma unroll
            for (int j = 0; j < 18; ++j) {
                float e = __expf((s[r][j] - mx) * ATTN_SCALE);
                s[r][j] = e;
                sum += e;
            }
            sum = warp_sum(sum);
            float inv = 1.f / sum;
#pragma unroll
            for (int j = 0; j < 18; ++j)
                Pw[r * 576 + lane + 32 * j] = s[r][j] * inv;
        }
        __syncwarp();

        // out[dh=lane][m+r] = sum_n P[r][n] * V[lane][n]
        float acc[4] = {0.f, 0.f, 0.f, 0.f};
        const float* Vr = Vsh + lane * KV_PAD;
        for (int n = 0; n < 576; n += 4) {
            float4 vv = *(const float4*)(Vr + n);
#pragma unroll
            for (int r = 0; r < 4; ++r) {
                float4 pp = *(const float4*)(Pw + r * 576 + n);
                acc[r] += pp.x * vv.x + pp.y * vv.y + pp.z * vv.z + pp.w * vv.w;
            }
        }
#pragma unroll
        for (int r = 0; r < 4; ++r)
            ob[(size_t)lane * HW + m + r] = acc[r];
        __syncwarp();   // all lanes done reading Pw before next iter overwrites
    }
}

// -------------------- launch --------------------
extern "C" void kernel_launch(void* const* d_in, const int* in_sizes, int n_in,
                              void* d_out, int out_size)
{
    (void)in_sizes; (void)n_in; (void)out_size;
    const float* x    = (const float*)d_in[0];
    const float* kv   = (const float*)d_in[1];
    const float* wq   = (const float*)d_in[2];
    const float* bq   = (const float*)d_in[3];
    const float* wk   = (const float*)d_in[4];
    const float* bk   = (const float*)d_in[5];
    const float* wv   = (const float*)d_in[6];
    const float* bv   = (const float*)d_in[7];
    const float* wdw  = (const float*)d_in[8];
    const float* bdw  = (const float*)d_in[9];
    const float* lnw  = (const float*)d_in[10];
    const float* lnb  = (const float*)d_in[11];
    const float* woff = (const float*)d_in[12];
    const float* wo   = (const float*)d_in[13];
    const float* bo   = (const float*)d_in[14];
    float* out = (float*)d_out;

    float *q, *kvs, *kb, *vb, *ao;
    cudaGetSymbolAddress((void**)&q,   g_q);
    cudaGetSymbolAddress((void**)&kvs, g_kvs);
    cudaGetSymbolAddress((void**)&kb,  g_k);
    cudaGetSymbolAddress((void**)&vb,  g_v);
    cudaGetSymbolAddress((void**)&ao,  g_ao);

    cudaFuncSetAttribute(attn_kernel, cudaFuncAttributeMaxDynamicSharedMemorySize,
                         ATTN_SMEM_BYTES);

    // 1) q projection
    gemm_bias_kernel<<<dim3(HW / 64, DIMC / 64, BATCH), 256>>>(wq, x, bq, q, HW);
    // 2) depthwise + LN + GELU + offsets + bilinear sample
    offset_sample_kernel<<<(64 * NKS) / 8, 256>>>(q, kv, wdw, bdw, lnw, lnb, woff, kvs);
    // 3,4) k/v projections on sampled kv
    gemm_bias_kernel<<<dim3(NKS / 64, DIMC / 64, BATCH), 256>>>(wk, kvs, bk, kb, NKS);
    gemm_bias_kernel<<<dim3(NKS / 64, DIMC / 64, BATCH), 256>>>(wv, kvs, bv, vb, NKS);
    // 5) attention
    attn_kernel<<<dim3(4, 64), 256, ATTN_SMEM_BYTES>>>(q, kb, vb, ao);
    // 6) output projection
    gemm_bias_kernel<<<dim3(HW / 64, DIMC / 64, BATCH), 256>>>(wo, ao, bo, out, HW);
}

// round 3
// speedup vs baseline: 1.6523x; 1.6523x over previous
#include <cuda_runtime.h>
#include <cuda_bf16.h>
#include <math.h>
#include <stdint.h>

#define BATCH 8
#define DIMC  256
#define HH    48
#define WWD   48
#define HW    2304
#define HEADS 8
#define DH    32
#define HKD   24
#define NKS   576
#define ATTN_SCALE 0.17677669529663687f

// ==================== scratch (device globals) ====================
__device__ float g_q  [BATCH * DIMC * HW];
__device__ float g_kvs[BATCH * DIMC * NKS];
__device__ float g_k  [BATCH * DIMC * NKS];
__device__ float g_v  [BATCH * DIMC * NKS];
__device__ float g_ao [BATCH * DIMC * HW];
// bf16 split operands for tensor-core attention
__device__ __nv_bfloat16 g_kthi[64 * NKS * DH];   // [bh][n][dh]
__device__ __nv_bfloat16 g_ktlo[64 * NKS * DH];
__device__ __nv_bfloat16 g_vhi [64 * DH * NKS];   // [bh][dh][n]
__device__ __nv_bfloat16 g_vlo [64 * DH * NKS];

// ==================== helpers ====================
__device__ __forceinline__ float warp_sum(float v) {
#pragma unroll
    for (int o = 16; o; o >>= 1) v += __shfl_xor_sync(0xffffffffu, v, o);
    return v;
}

// pack two fp32 to bf16x2: lo16 = bf16(a), hi16 = bf16(b)
__device__ __forceinline__ uint32_t pack_bf16(float a, float b) {
    uint32_t r;
    asm("cvt.rn.satfinite.bf16x2.f32 %0, %1, %2;" : "=r"(r) : "f"(b), "f"(a));
    return r;
}

// mma.sync m16n8k16 bf16 (works on baseline sm_103 target)
__device__ __forceinline__ void mma16816(float* d, const uint32_t* a, const uint32_t* b,
                                         const float* c) {
    asm volatile("mma.sync.aligned.m16n8k16.row.col.f32.bf16.bf16.f32 "
        "{%0,%1,%2,%3}, {%4,%5,%6,%7}, {%8,%9}, {%10,%11,%12,%13};"
        : "=f"(d[0]), "=f"(d[1]), "=f"(d[2]), "=f"(d[3])
        : "r"(a[0]), "r"(a[1]), "r"(a[2]), "r"(a[3]),
          "r"(b[0]), "r"(b[1]),
          "f"(c[0]), "f"(c[1]), "f"(c[2]), "f"(c[3]));
}

// ==================== batched GEMM (fp32) ====================
__global__ void gemm_bias_kernel(const float* __restrict__ W,
                                 const float* __restrict__ X,
                                 const float* __restrict__ bias,
                                 float* __restrict__ C, int N)
{
    __shared__ float As[16][64];
    __shared__ float Bs[16][64];
    const int n0 = blockIdx.x * 64;
    const int m0 = blockIdx.y * 64;
    X += (size_t)blockIdx.z * DIMC * N;
    C += (size_t)blockIdx.z * DIMC * N;
    const int tid = threadIdx.x;
    const int tx = tid & 15, ty = tid >> 4;
    float acc[4][4] = {};
    for (int k0 = 0; k0 < DIMC; k0 += 16) {
        {
            int mm = tid >> 2, kq = tid & 3;
            float4 a = *(const float4*)(W + (size_t)(m0 + mm) * DIMC + k0 + kq * 4);
            As[kq * 4 + 0][mm] = a.x; As[kq * 4 + 1][mm] = a.y;
            As[kq * 4 + 2][mm] = a.z; As[kq * 4 + 3][mm] = a.w;
        }
        {
            int r = tid >> 4, cq = tid & 15;
            *(float4*)(&Bs[r][cq * 4]) = *(const float4*)(X + (size_t)(k0 + r) * N + n0 + cq * 4);
        }
        __syncthreads();
#pragma unroll
        for (int kk = 0; kk < 16; ++kk) {
            float4 a = *(const float4*)(&As[kk][ty * 4]);
            float4 b = *(const float4*)(&Bs[kk][tx * 4]);
            float av[4] = {a.x, a.y, a.z, a.w};
            float bv[4] = {b.x, b.y, b.z, b.w};
#pragma unroll
            for (int i = 0; i < 4; ++i)
#pragma unroll
                for (int j = 0; j < 4; ++j) acc[i][j] += av[i] * bv[j];
        }
        __syncthreads();
    }
#pragma unroll
    for (int i = 0; i < 4; ++i) {
        float bi = bias[m0 + ty * 4 + i];
        float4 o = make_float4(acc[i][0] + bi, acc[i][1] + bi, acc[i][2] + bi, acc[i][3] + bi);
        *(float4*)(C + (size_t)(m0 + ty * 4 + i) * N + n0 + tx * 4) = o;
    }
}

// ==================== offset + sample ====================
__global__ void offset_sample_kernel(const float* __restrict__ q,
                                     const float* __restrict__ kv,
                                     const float* __restrict__ w_dw,
                                     const float* __restrict__ b_dw,
                                     const float* __restrict__ ln_w,
                                     const float* __restrict__ ln_b,
                                     const float* __restrict__ w_off,
                                     float* __restrict__ kvs)
{
    __shared__ float s_wdw[32 * 25];
    __shared__ float s_bdw[32], s_lnw[32], s_lnb[32], s_woff[64];
    const int tid = threadIdx.x;
    for (int i = tid; i < 800; i += 256) s_wdw[i] = w_dw[i];
    if (tid < 32) { s_bdw[tid] = b_dw[tid]; s_lnw[tid] = ln_w[tid]; s_lnb[tid] = ln_b[tid]; }
    if (tid < 64) s_woff[tid] = w_off[tid];
    __syncthreads();
    const int wid  = blockIdx.x * 8 + (tid >> 5);
    const int lane = tid & 31;
    const int bh  = wid / NKS;
    const int pos = wid - bh * NKS;
    const int hk  = pos / HKD;
    const int wk  = pos - hk * HKD;
    const int b   = bh >> 3;
    const int h   = bh & 7;
    const float* qc = q + ((size_t)(b * DIMC + h * DH + lane)) * HW;
    float t = 0.f;
    const int y0 = hk * 2 - 2, x0 = wk * 2 - 2;
#pragma unroll
    for (int i = 0; i < 5; ++i) {
        int yy = y0 + i;
        if ((unsigned)yy < (unsigned)HH) {
#pragma unroll
            for (int j = 0; j < 5; ++j) {
                int xx = x0 + j;
                if ((unsigned)xx < (unsigned)WWD)
                    t += qc[yy * WWD + xx] * s_wdw[lane * 25 + i * 5 + j];
            }
        }
    }
    t += s_bdw[lane];
    float mu  = warp_sum(t) * (1.f / 32.f);
    float d   = t - mu;
    float var = warp_sum(d * d) * (1.f / 32.f);
    t = d * rsqrtf(var + 1e-5f) * s_lnw[lane] + s_lnb[lane];
    t = 0.5f * t * (1.f + erff(t * 0.70710678118654752f));
    float o0 = warp_sum(s_woff[lane] * t);
    float o1 = warp_sum(s_woff[32 + lane] * t);
    const float refy = (0.5f + (float)hk) * (2.f / 23.f) - 1.f;
    const float refx = (0.5f + (float)wk) * (2.f / 23.f) - 1.f;
    float py = fminf(fmaxf(o0 + refy, -1.f), 1.f);
    float px = fminf(fmaxf(o1 + refx, -1.f), 1.f);
    float gx = (px + 1.f) * 0.5f * 47.f;
    float gy = (py + 1.f) * 0.5f * 47.f;
    float fx = floorf(gx), fy = floorf(gy);
    float wx = gx - fx,   wy = gy - fy;
    int x0i = min(max((int)fx, 0), 47);
    int x1i = min(max((int)fx + 1, 0), 47);
    int y0i = min(max((int)fy, 0), 47);
    int y1i = min(max((int)fy + 1, 0), 47);
    const float* kvc = kv + ((size_t)(b * DIMC + h * DH + lane)) * HW;
    float v00 = kvc[y0i * WWD + x0i];
    float v01 = kvc[y0i * WWD + x1i];
    float v10 = kvc[y1i * WWD + x0i];
    float v11 = kvc[y1i * WWD + x1i];
    float val = (1.f - wx) * (1.f - wy) * v00 + wx * (1.f - wy) * v01 +
                (1.f - wx) * wy * v10 + wx * wy * v11;
    kvs[((size_t)(b * DIMC + h * DH + lane)) * NKS + pos] = val;
}

// ==================== bf16 split conversions ====================
__global__ void convert_k_kernel(const float* __restrict__ k,
                                 __nv_bfloat16* __restrict__ kthi,
                                 __nv_bfloat16* __restrict__ ktlo)
{
    __shared__ float s[32][65];
    const int bh = blockIdx.x;
    const int b = bh >> 3, h = bh & 7;
    const float* kb = k + (size_t)(b * DIMC + h * DH) * NKS;
    const size_t obase = (size_t)bh * NKS * DH;
    for (int n0 = 0; n0 < NKS; n0 += 64) {
        for (int i = threadIdx.x; i < 2048; i += 256) {
            int dh = i >> 6, nn = i & 63;
            s[dh][nn] = kb[(size_t)dh * NKS + n0 + nn];
        }
        __syncthreads();
        for (int i = threadIdx.x; i < 2048; i += 256) {
            int r = i >> 5, dh = i & 31;
            float x = s[dh][r];
            __nv_bfloat16 hi = __float2bfloat16(x);
            float lo = x - __bfloat162float(hi);
            kthi[obase + (size_t)(n0 + r) * DH + dh] = hi;
            ktlo[obase + (size_t)(n0 + r) * DH + dh] = __float2bfloat16(lo);
        }
        __syncthreads();
    }
}

__global__ void convert_v_kernel(const float* __restrict__ v,
                                 __nv_bfloat16* __restrict__ vhi,
                                 __nv_bfloat16* __restrict__ vlo)
{
    const int bh = blockIdx.x;
    const int b = bh >> 3, h = bh & 7;
    const float* vb = v + (size_t)(b * DIMC + h * DH) * NKS;
    const size_t obase = (size_t)bh * DH * NKS;
    for (int i = threadIdx.x; i < DH * NKS; i += 256) {
        float x = vb[i];
        __nv_bfloat16 hi = __float2bfloat16(x);
        float lo = x - __bfloat162float(hi);
        vhi[obase + i] = hi;
        vlo[obase + i] = __float2bfloat16(lo);
    }
}

// ==================== mma.sync attention ====================
// grid (18, 64), 256 threads (8 warps x 16 rows = 128 q rows per CTA).
// smem: K^T hi/lo [576][stride 40] bf16, V hi/lo [32][stride 584] bf16,
//       Q stage [128][stride 40] bf16 hi/lo (reused as fp32 output staging).
#define A_KHI   0
#define A_KLO   46080
#define A_VHI   92160
#define A_VLO   129536
#define A_QSTG  166912
#define A_SMEM  187392

__global__ void __launch_bounds__(256)
attn_mma_kernel(const float* __restrict__ q,
                const uint32_t* __restrict__ kthi, const uint32_t* __restrict__ ktlo,
                const uint32_t* __restrict__ vhi,  const uint32_t* __restrict__ vlo,
                float* __restrict__ out)
{
    extern __shared__ char smem[];
    uint32_t* skh = (uint32_t*)(smem + A_KHI);    // [576][20] words
    uint32_t* skl = (uint32_t*)(smem + A_KLO);
    uint32_t* svh = (uint32_t*)(smem + A_VHI);    // [32][292] words
    uint32_t* svl = (uint32_t*)(smem + A_VLO);
    __nv_bfloat16* sqh = (__nv_bfloat16*)(smem + A_QSTG);          // [128][40]
    __nv_bfloat16* sql = (__nv_bfloat16*)(smem + A_QSTG + 10240);
    float* ostg = (float*)(smem + A_QSTG);        // [32][132] f32 (reuse)

    const int tid  = threadIdx.x;
    const int lane = tid & 31, warp = tid >> 5;
    const int bh = blockIdx.y, b = bh >> 3, h = bh & 7;
    const int m0 = blockIdx.x * 128;

    // ---- K^T hi/lo into smem (row stride 20 words) ----
    const uint32_t* gkh = kthi + (size_t)bh * 9216;
    const uint32_t* gkl = ktlo + (size_t)bh * 9216;
    for (int i = tid; i < 9216; i += 256) {
        int n = i >> 4, w = i & 15;
        skh[n * 20 + w] = gkh[i];
        skl[n * 20 + w] = gkl[i];
    }
    // ---- V hi/lo into smem (row stride 292 words) ----
    const uint32_t* gvh = vhi + (size_t)bh * 9216;
    const uint32_t* gvl = vlo + (size_t)bh * 9216;
    for (int i = tid; i < 9216; i += 256) {
        int dh = i / 288, w = i - dh * 288;
        svh[dh * 292 + w] = gvh[i];
        svl[dh * 292 + w] = gvl[i];
    }
    // ---- Q tile: fp32 -> bf16 hi/lo staged [m][dh] ----
    const float* qb = q + (size_t)(b * DIMC + h * DH) * HW + m0;
    for (int i = tid; i < 4096; i += 256) {
        int dh = i >> 7, m = i & 127;
        float x = qb[(size_t)dh * HW + m];
        __nv_bfloat16 hi = __float2bfloat16(x);
        float lo = x - __bfloat162float(hi);
        sqh[m * 40 + dh] = hi;
        sql[m * 40 + dh] = __float2bfloat16(lo);
    }
    __syncthreads();

    // ---- Q fragments (A of m16n8k16), k=32 => 2 k-steps ----
    const int r = lane >> 2, c = lane & 3;
    const int mrow = warp * 16;
    uint32_t qfh[2][4], qfl[2][4];
#pragma unroll
    for (int ks = 0; ks < 2; ++ks) {
        int k0 = ks * 16 + c * 2;
        qfh[ks][0] = *(const uint32_t*)(sqh + (mrow + r) * 40 + k0);
        qfh[ks][1] = *(const uint32_t*)(sqh + (mrow + r + 8) * 40 + k0);
        qfh[ks][2] = *(const uint32_t*)(sqh + (mrow + r) * 40 + k0 + 8);
        qfh[ks][3] = *(const uint32_t*)(sqh + (mrow + r + 8) * 40 + k0 + 8);
        qfl[ks][0] = *(const uint32_t*)(sql + (mrow + r) * 40 + k0);
        qfl[ks][1] = *(const uint32_t*)(sql + (mrow + r + 8) * 40 + k0);
        qfl[ks][2] = *(const uint32_t*)(sql + (mrow + r) * 40 + k0 + 8);
        qfl[ks][3] = *(const uint32_t*)(sql + (mrow + r + 8) * 40 + k0 + 8);
    }

    float O[4][4] = {};
    float rs0 = 0.f, rs1 = 0.f;

    for (int chunk = 0; chunk < 9; ++chunk) {
        const int n0 = chunk * 64;
        float S[8][4];
#pragma unroll
        for (int nb = 0; nb < 8; ++nb)
#pragma unroll
            for (int i = 0; i < 4; ++i) S[nb][i] = 0.f;

        // S = Qh*Kh + Qh*Kl + Ql*Kh
#pragma unroll
        for (int nb = 0; nb < 8; ++nb) {
            const uint32_t* kr  = skh + (n0 + nb * 8 + r) * 20 + c;
            const uint32_t* krl = skl + (n0 + nb * 8 + r) * 20 + c;
#pragma unroll
            for (int ks = 0; ks < 2; ++ks) {
                uint32_t bh2[2] = { kr[ks * 8],  kr[ks * 8 + 4]  };
                uint32_t bl2[2] = { krl[ks * 8], krl[ks * 8 + 4] };
                mma16816(S[nb], qfh[ks], bh2, S[nb]);
                mma16816(S[nb], qfh[ks], bl2, S[nb]);
                mma16816(S[nb], qfl[ks], bh2, S[nb]);
            }
        }

        // exp (no-max softmax; logits tiny) + PV per 16-k window
#pragma unroll
        for (int j = 0; j < 4; ++j) {
            float e[8];
#pragma unroll
            for (int i = 0; i < 4; ++i) {
                e[i]     = __expf(S[2 * j][i]     * ATTN_SCALE);
                e[4 + i] = __expf(S[2 * j + 1][i] * ATTN_SCALE);
            }
            rs0 += e[0] + e[1] + e[4] + e[5];
            rs1 += e[2] + e[3] + e[6] + e[7];

            uint32_t ph[4], pl[4];
#pragma unroll
            for (int i = 0; i < 4; ++i) {
                float a = e[2 * i], bb = e[2 * i + 1];
                uint32_t hp = pack_bf16(a, bb);
                float ra = a  - __uint_as_float(hp << 16);
                float rb = bb - __uint_as_float(hp & 0xffff0000u);
                ph[i] = hp;
                pl[i] = pack_bf16(ra, rb);
            }

            const int kw = n0 / 2 + j * 8 + c;   // word offset within V row
#pragma unroll
            for (int dhb = 0; dhb < 4; ++dhb) {
                const uint32_t* vr  = svh + (dhb * 8 + r) * 292 + kw;
                const uint32_t* vrl = svl + (dhb * 8 + r) * 292 + kw;
                uint32_t bh2[2] = { vr[0],  vr[4]  };
                uint32_t bl2[2] = { vrl[0], vrl[4] };
                mma16816(O[dhb], ph, bh2, O[dhb]);
                mma16816(O[dhb], ph, bl2, O[dhb]);
                mma16816(O[dhb], pl, bh2, O[dhb]);
            }
        }
    }

    // ---- rowsum reduce over the 4 lanes of each row group ----
    rs0 += __shfl_xor_sync(0xffffffffu, rs0, 1);
    rs0 += __shfl_xor_sync(0xffffffffu, rs0, 2);
    rs1 += __shfl_xor_sync(0xffffffffu, rs1, 1);
    rs1 += __shfl_xor_sync(0xffffffffu, rs1, 2);
    float inv0 = 1.f / rs0, inv1 = 1.f / rs1;

    // ---- normalize + transpose via smem + coalesced store ----
    __syncthreads();   // everyone past Q-frag/smem reads before ostg overwrites
#pragma unroll
    for (int dhb = 0; dhb < 4; ++dhb) {
        int dh0 = dhb * 8 + c * 2;
        ostg[dh0 * 132 + mrow + r]           = O[dhb][0] * inv0;
        ostg[(dh0 + 1) * 132 + mrow + r]     = O[dhb][1] * inv0;
        ostg[dh0 * 132 + mrow + r + 8]       = O[dhb][2] * inv1;
        ostg[(dh0 + 1) * 132 + mrow + r + 8] = O[dhb][3] * inv1;
    }
    __syncthreads();
    float* ob = out + (size_t)(b * DIMC + h * DH) * HW + m0;
    for (int i = tid; i < 4096; i += 256) {
        int dh = i >> 7, m = i & 127;
        ob[(size_t)dh * HW + m] = ostg[dh * 132 + m];
    }
}

// ==================== launch ====================
extern "C" void kernel_launch(void* const* d_in, const int* in_sizes, int n_in,
                              void* d_out, int out_size)
{
    (void)in_sizes; (void)n_in; (void)out_size;
    const float* x    = (const float*)d_in[0];
    const float* kv   = (const float*)d_in[1];
    const float* wq   = (const float*)d_in[2];
    const float* bq   = (const float*)d_in[3];
    const float* wk   = (const float*)d_in[4];
    const float* bk   = (const float*)d_in[5];
    const float* wv   = (const float*)d_in[6];
    const float* bv   = (const float*)d_in[7];
    const float* wdw  = (const float*)d_in[8];
    const float* bdw  = (const float*)d_in[9];
    const float* lnw  = (const float*)d_in[10];
    const float* lnb  = (const float*)d_in[11];
    const float* woff = (const float*)d_in[12];
    const float* wo   = (const float*)d_in[13];
    const float* bo   = (const float*)d_in[14];
    float* out = (float*)d_out;

    float *q, *kvs, *kb, *vb, *ao;
    __nv_bfloat16 *kthi, *ktlo, *vhi, *vlo;
    cudaGetSymbolAddress((void**)&q,    g_q);
    cudaGetSymbolAddress((void**)&kvs,  g_kvs);
    cudaGetSymbolAddress((void**)&kb,   g_k);
    cudaGetSymbolAddress((void**)&vb,   g_v);
    cudaGetSymbolAddress((void**)&ao,   g_ao);
    cudaGetSymbolAddress((void**)&kthi, g_kthi);
    cudaGetSymbolAddress((void**)&ktlo, g_ktlo);
    cudaGetSymbolAddress((void**)&vhi,  g_vhi);
    cudaGetSymbolAddress((void**)&vlo,  g_vlo);

    cudaFuncSetAttribute(attn_mma_kernel, cudaFuncAttributeMaxDynamicSharedMemorySize, A_SMEM);

    // 1) q projection
    gemm_bias_kernel<<<dim3(HW / 64, DIMC / 64, BATCH), 256>>>(wq, x, bq, q, HW);
    // 2) depthwise + LN + GELU + offsets + bilinear sample
    offset_sample_kernel<<<(64 * NKS) / 8, 256>>>(q, kv, wdw, bdw, lnw, lnb, woff, kvs);
    // 3,4) k/v projections
    gemm_bias_kernel<<<dim3(NKS / 64, DIMC / 64, BATCH), 256>>>(wk, kvs, bk, kb, NKS);
    gemm_bias_kernel<<<dim3(NKS / 64, DIMC / 64, BATCH), 256>>>(wv, kvs, bv, vb, NKS);
    // 4b) bf16 hi/lo conversions
    convert_k_kernel<<<64, 256>>>(kb, kthi, ktlo);
    convert_v_kernel<<<64, 256>>>(vb, vhi, vlo);
    // 5) attention on mma.sync bf16 (split fp32 emulation)
    attn_mma_kernel<<<dim3(HW / 128, 64), 256, A_SMEM>>>(
        q, (const uint32_t*)kthi, (const uint32_t*)ktlo,
        (const uint32_t*)vhi, (const uint32_t*)vlo, ao);
    // 6) output projection
    gemm_bias_kernel<<<dim3(HW / 64, DIMC / 64, BATCH), 256>>>(wo, ao, bo, out, HW);
}

// round 4
// speedup vs baseline: 1.6945x; 1.0256x over previous
#include <cuda_runtime.h>
#include <cuda_bf16.h>
#include <math.h>
#include <stdint.h>

#define BATCH 8
#define DIMC  256
#define HH    48
#define WWD   48
#define HW    2304
#define HEADS 8
#define DH    32
#define HKD   24
#define NKS   576
#define ATTN_SCALE 0.17677669529663687f

// ==================== scratch (device globals) ====================
__device__ float g_q  [BATCH * DIMC * HW];
__device__ float g_kvs[BATCH * DIMC * NKS];
__device__ float g_ao [BATCH * DIMC * HW];
__device__ __nv_bfloat16 g_kthi[64 * NKS * DH];   // [bh][n][dh]
__device__ __nv_bfloat16 g_ktlo[64 * NKS * DH];
__device__ __nv_bfloat16 g_vhi [64 * DH * NKS];   // [bh][dh][n]
__device__ __nv_bfloat16 g_vlo [64 * DH * NKS];

// ==================== helpers ====================
__device__ __forceinline__ float warp_sum(float v) {
#pragma unroll
    for (int o = 16; o; o >>= 1) v += __shfl_xor_sync(0xffffffffu, v, o);
    return v;
}
__device__ __forceinline__ uint32_t smem_u32(const void* p) {
    uint32_t a;
    asm("{ .reg .u64 t; cvta.to.shared.u64 t, %1; cvt.u32.u64 %0, t; }" : "=r"(a) : "l"(p));
    return a;
}
// pack two fp32 to bf16x2: lo16 = bf16(a), hi16 = bf16(b)
__device__ __forceinline__ uint32_t pack_bf16(float a, float b) {
    uint32_t r;
    asm("cvt.rn.satfinite.bf16x2.f32 %0, %1, %2;" : "=r"(r) : "f"(b), "f"(a));
    return r;
}
__device__ __forceinline__ void mma16816(float* d, const uint32_t* a, const uint32_t* b,
                                         const float* c) {
    asm volatile("mma.sync.aligned.m16n8k16.row.col.f32.bf16.bf16.f32 "
        "{%0,%1,%2,%3}, {%4,%5,%6,%7}, {%8,%9}, {%10,%11,%12,%13};"
        : "=f"(d[0]), "=f"(d[1]), "=f"(d[2]), "=f"(d[3])
        : "r"(a[0]), "r"(a[1]), "r"(a[2]), "r"(a[3]),
          "r"(b[0]), "r"(b[1]),
          "f"(c[0]), "f"(c[1]), "f"(c[2]), "f"(c[3]));
}
__device__ __forceinline__ void ldsm_x4(uint32_t& r0, uint32_t& r1, uint32_t& r2,
                                        uint32_t& r3, uint32_t addr) {
    asm volatile("ldmatrix.sync.aligned.m8n8.x4.shared.b16 {%0,%1,%2,%3}, [%4];"
                 : "=r"(r0), "=r"(r1), "=r"(r2), "=r"(r3) : "r"(addr));
}

// ==================== batched GEMM (fp32): q and o projections ====================
__global__ void gemm_bias_kernel(const float* __restrict__ W,
                                 const float* __restrict__ X,
                                 const float* __restrict__ bias,
                                 float* __restrict__ C, int N)
{
    __shared__ float As[16][64];
    __shared__ float Bs[16][64];
    const int n0 = blockIdx.x * 64;
    const int m0 = blockIdx.y * 64;
    X += (size_t)blockIdx.z * DIMC * N;
    C += (size_t)blockIdx.z * DIMC * N;
    const int tid = threadIdx.x;
    const int tx = tid & 15, ty = tid >> 4;
    float acc[4][4] = {};
    for (int k0 = 0; k0 < DIMC; k0 += 16) {
        {
            int mm = tid >> 2, kq = tid & 3;
            float4 a = *(const float4*)(W + (size_t)(m0 + mm) * DIMC + k0 + kq * 4);
            As[kq * 4 + 0][mm] = a.x; As[kq * 4 + 1][mm] = a.y;
            As[kq * 4 + 2][mm] = a.z; As[kq * 4 + 3][mm] = a.w;
        }
        {
            int r = tid >> 4, cq = tid & 15;
            *(float4*)(&Bs[r][cq * 4]) = *(const float4*)(X + (size_t)(k0 + r) * N + n0 + cq * 4);
        }
        __syncthreads();
#pragma unroll
        for (int kk = 0; kk < 16; ++kk) {
            float4 a = *(const float4*)(&As[kk][ty * 4]);
            float4 b = *(const float4*)(&Bs[kk][tx * 4]);
            float av[4] = {a.x, a.y, a.z, a.w};
            float bv[4] = {b.x, b.y, b.z, b.w};
#pragma unroll
            for (int i = 0; i < 4; ++i)
#pragma unroll
                for (int j = 0; j < 4; ++j) acc[i][j] += av[i] * bv[j];
        }
        __syncthreads();
    }
#pragma unroll
    for (int i = 0; i < 4; ++i) {
        float bi = bias[m0 + ty * 4 + i];
        float4 o = make_float4(acc[i][0] + bi, acc[i][1] + bi, acc[i][2] + bi, acc[i][3] + bi);
        *(float4*)(C + (size_t)(m0 + ty * 4 + i) * N + n0 + tx * 4) = o;
    }
}

// ==================== fused k+v GEMM with bf16 hi/lo split epilogue ====================
// grid (9, 8, 8): y 0-3 => K rows 0-255, y 4-7 => V rows 0-255. Writes split arrays only.
__global__ void gemm_kv_kernel(const float* __restrict__ Wk, const float* __restrict__ bk,
                               const float* __restrict__ Wv, const float* __restrict__ bv,
                               const float* __restrict__ X,
                               __nv_bfloat16* __restrict__ kthi, __nv_bfloat16* __restrict__ ktlo,
                               __nv_bfloat16* __restrict__ vhi,  __nv_bfloat16* __restrict__ vlo)
{
    __shared__ float As[16][64];
    __shared__ float Bs[16][64];
    const int n0 = blockIdx.x * 64;
    const bool isV = blockIdx.y >= 4;
    const int m0 = (blockIdx.y & 3) * 64;
    const float* W  = isV ? Wv : Wk;
    const float* bb = isV ? bv : bk;
    X += (size_t)blockIdx.z * DIMC * NKS;
    const int tid = threadIdx.x;
    const int tx = tid & 15, ty = tid >> 4;
    float acc[4][4] = {};
    for (int k0 = 0; k0 < DIMC; k0 += 16) {
        {
            int mm = tid >> 2, kq = tid & 3;
            float4 a = *(const float4*)(W + (size_t)(m0 + mm) * DIMC + k0 + kq * 4);
            As[kq * 4 + 0][mm] = a.x; As[kq * 4 + 1][mm] = a.y;
            As[kq * 4 + 2][mm] = a.z; As[kq * 4 + 3][mm] = a.w;
        }
        {
            int r = tid >> 4, cq = tid & 15;
            *(float4*)(&Bs[r][cq * 4]) = *(const float4*)(X + (size_t)(k0 + r) * NKS + n0 + cq * 4);
        }
        __syncthreads();
#pragma unroll
        for (int kk = 0; kk < 16; ++kk) {
            float4 a = *(const float4*)(&As[kk][ty * 4]);
            float4 b = *(const float4*)(&Bs[kk][tx * 4]);
            float av[4] = {a.x, a.y, a.z, a.w};
            float bv2[4] = {b.x, b.y, b.z, b.w};
#pragma unroll
            for (int i = 0; i < 4; ++i)
#pragma unroll
                for (int j = 0; j < 4; ++j) acc[i][j] += av[i] * bv2[j];
        }
        __syncthreads();
    }
    // epilogue: add bias, split to bf16 hi/lo, write transposed layouts
    const int mbase = m0 + ty * 4;             // channel row base (4 consecutive, within a 32-block)
    const int h  = mbase >> 5;
    const int dh0 = mbase & 31;
    const int bh = blockIdx.z * 8 + h;
    float hi4[4][4], lo4[4][4];
#pragma unroll
    for (int i = 0; i < 4; ++i) {
        float bi = bb[mbase + i];
#pragma unroll
        for (int j = 0; j < 4; ++j) {
            float x = acc[i][j] + bi;
            float hv = __bfloat162float(__float2bfloat16(x));
            hi4[i][j] = hv;
            lo4[i][j] = x - hv;
        }
    }
    if (!isV) {
        // kthi[bh][n][dh]: for each n (j), 4 consecutive dh
        __nv_bfloat16* oh = kthi + (size_t)bh * NKS * DH;
        __nv_bfloat16* ol = ktlo + (size_t)bh * NKS * DH;
#pragma unroll
        for (int j = 0; j < 4; ++j) {
            int n = n0 + tx * 4 + j;
            uint32_t p0 = pack_bf16(hi4[0][j], hi4[1][j]);
            uint32_t p1 = pack_bf16(hi4[2][j], hi4[3][j]);
            *(uint2*)(oh + (size_t)n * DH + dh0) = make_uint2(p0, p1);
            uint32_t q0 = pack_bf16(lo4[0][j], lo4[1][j]);
            uint32_t q1 = pack_bf16(lo4[2][j], lo4[3][j]);
            *(uint2*)(ol + (size_t)n * DH + dh0) = make_uint2(q0, q1);
        }
    } else {
        // vhi[bh][dh][n]: for each dh (i), 4 consecutive n
        __nv_bfloat16* oh = vhi + (size_t)bh * DH * NKS;
        __nv_bfloat16* ol = vlo + (size_t)bh * DH * NKS;
#pragma unroll
        for (int i = 0; i < 4; ++i) {
            int n = n0 + tx * 4;
            uint32_t p0 = pack_bf16(hi4[i][0], hi4[i][1]);
            uint32_t p1 = pack_bf16(hi4[i][2], hi4[i][3]);
            *(uint2*)(oh + (size_t)(dh0 + i) * NKS + n) = make_uint2(p0, p1);
            uint32_t q0 = pack_bf16(lo4[i][0], lo4[i][1]);
            uint32_t q1 = pack_bf16(lo4[i][2], lo4[i][3]);
            *(uint2*)(ol + (size_t)(dh0 + i) * NKS + n) = make_uint2(q0, q1);
        }
    }
}

// ==================== offset + sample ====================
__global__ void offset_sample_kernel(const float* __restrict__ q,
                                     const float* __restrict__ kv,
                                     const float* __restrict__ w_dw,
                                     const float* __restrict__ b_dw,
                                     const float* __restrict__ ln_w,
                                     const float* __restrict__ ln_b,
                                     const float* __restrict__ w_off,
                                     float* __restrict__ kvs)
{
    __shared__ float s_wdw[32 * 25];
    __shared__ float s_bdw[32], s_lnw[32], s_lnb[32], s_woff[64];
    const int tid = threadIdx.x;
    for (int i = tid; i < 800; i += 256) s_wdw[i] = w_dw[i];
    if (tid < 32) { s_bdw[tid] = b_dw[tid]; s_lnw[tid] = ln_w[tid]; s_lnb[tid] = ln_b[tid]; }
    if (tid < 64) s_woff[tid] = w_off[tid];
    __syncthreads();
    const int wid  = blockIdx.x * 8 + (tid >> 5);
    const int lane = tid & 31;
    const int bh  = wid / NKS;
    const int pos = wid - bh * NKS;
    const int hk  = pos / HKD;
    const int wk  = pos - hk * HKD;
    const int b   = bh >> 3;
    const int h   = bh & 7;
    const float* qc = q + ((size_t)(b * DIMC + h * DH + lane)) * HW;
    float t = 0.f;
    const int y0 = hk * 2 - 2, x0 = wk * 2 - 2;
#pragma unroll
    for (int i = 0; i < 5; ++i) {
        int yy = y0 + i;
        if ((unsigned)yy < (unsigned)HH) {
#pragma unroll
            for (int j = 0; j < 5; ++j) {
                int xx = x0 + j;
                if ((unsigned)xx < (unsigned)WWD)
                    t += qc[yy * WWD + xx] * s_wdw[lane * 25 + i * 5 + j];
            }
        }
    }
    t += s_bdw[lane];
    float mu  = warp_sum(t) * (1.f / 32.f);
    float d   = t - mu;
    float var = warp_sum(d * d) * (1.f / 32.f);
    t = d * rsqrtf(var + 1e-5f) * s_lnw[lane] + s_lnb[lane];
    t = 0.5f * t * (1.f + erff(t * 0.70710678118654752f));
    float o0 = warp_sum(s_woff[lane] * t);
    float o1 = warp_sum(s_woff[32 + lane] * t);
    const float refy = (0.5f + (float)hk) * (2.f / 23.f) - 1.f;
    const float refx = (0.5f + (float)wk) * (2.f / 23.f) - 1.f;
    float py = fminf(fmaxf(o0 + refy, -1.f), 1.f);
    float px = fminf(fmaxf(o1 + refx, -1.f), 1.f);
    float gx = (px + 1.f) * 0.5f * 47.f;
    float gy = (py + 1.f) * 0.5f * 47.f;
    float fx = floorf(gx), fy = floorf(gy);
    float wx = gx - fx,   wy = gy - fy;
    int x0i = min(max((int)fx, 0), 47);
    int x1i = min(max((int)fx + 1, 0), 47);
    int y0i = min(max((int)fy, 0), 47);
    int y1i = min(max((int)fy + 1, 0), 47);
    const float* kvc = kv + ((size_t)(b * DIMC + h * DH + lane)) * HW;
    float v00 = kvc[y0i * WWD + x0i];
    float v01 = kvc[y0i * WWD + x1i];
    float v10 = kvc[y1i * WWD + x0i];
    float v11 = kvc[y1i * WWD + x1i];
    float val = (1.f - wx) * (1.f - wy) * v00 + wx * (1.f - wy) * v01 +
                (1.f - wx) * wy * v10 + wx * wy * v11;
    kvs[((size_t)(b * DIMC + h * DH + lane)) * NKS + pos] = val;
}

// ==================== mma.sync attention with ldmatrix ====================
#define A_KHI   0
#define A_KLO   46080
#define A_VHI   92160
#define A_VLO   129536
#define A_QSTG  166912
#define A_SMEM  187392

__global__ void __launch_bounds__(256)
attn_mma_kernel(const float* __restrict__ q,
                const uint32_t* __restrict__ kthi, const uint32_t* __restrict__ ktlo,
                const uint32_t* __restrict__ vhi,  const uint32_t* __restrict__ vlo,
                float* __restrict__ out)
{
    extern __shared__ char smem[];
    uint32_t* skh = (uint32_t*)(smem + A_KHI);    // [576][20] words
    uint32_t* skl = (uint32_t*)(smem + A_KLO);
    uint32_t* svh = (uint32_t*)(smem + A_VHI);    // [32][292] words
    uint32_t* svl = (uint32_t*)(smem + A_VLO);
    __nv_bfloat16* sqh = (__nv_bfloat16*)(smem + A_QSTG);          // [128][40]
    __nv_bfloat16* sql = (__nv_bfloat16*)(smem + A_QSTG + 10240);
    float* ostg = (float*)(smem + A_QSTG);        // [32][132] f32 (reuse)

    const int tid  = threadIdx.x;
    const int lane = tid & 31, warp = tid >> 5;
    const int bh = blockIdx.y, b = bh >> 3, h = bh & 7;
    const int m0 = blockIdx.x * 128;

    // ---- K^T hi/lo into smem ----
    const uint32_t* gkh = kthi + (size_t)bh * 9216;
    const uint32_t* gkl = ktlo + (size_t)bh * 9216;
    for (int i = tid; i < 9216; i += 256) {
        int n = i >> 4, w = i & 15;
        skh[n * 20 + w] = gkh[i];
        skl[n * 20 + w] = gkl[i];
    }
    // ---- V hi/lo into smem ----
    const uint32_t* gvh = vhi + (size_t)bh * 9216;
    const uint32_t* gvl = vlo + (size_t)bh * 9216;
    for (int i = tid; i < 9216; i += 256) {
        int dh = i / 288, w = i - dh * 288;
        svh[dh * 292 + w] = gvh[i];
        svl[dh * 292 + w] = gvl[i];
    }
    // ---- Q tile: fp32 -> bf16 hi/lo staged [m][dh] ----
    const float* qb = q + (size_t)(b * DIMC + h * DH) * HW + m0;
    for (int i = tid; i < 4096; i += 256) {
        int dh = i >> 7, m = i & 127;
        float x = qb[(size_t)dh * HW + m];
        __nv_bfloat16 hi = __float2bfloat16(x);
        float lo = x - __bfloat162float(hi);
        sqh[m * 40 + dh] = hi;
        sql[m * 40 + dh] = __float2bfloat16(lo);
    }
    __syncthreads();

    // ---- Q fragments ----
    const int r = lane >> 2, c = lane & 3;
    const int mrow = warp * 16;
    uint32_t qfh[2][4], qfl[2][4];
#pragma unroll
    for (int ks = 0; ks < 2; ++ks) {
        int k0 = ks * 16 + c * 2;
        qfh[ks][0] = *(const uint32_t*)(sqh + (mrow + r) * 40 + k0);
        qfh[ks][1] = *(const uint32_t*)(sqh + (mrow + r + 8) * 40 + k0);
        qfh[ks][2] = *(const uint32_t*)(sqh + (mrow + r) * 40 + k0 + 8);
        qfh[ks][3] = *(const uint32_t*)(sqh + (mrow + r + 8) * 40 + k0 + 8);
        qfl[ks][0] = *(const uint32_t*)(sql + (mrow + r) * 40 + k0);
        qfl[ks][1] = *(const uint32_t*)(sql + (mrow + r + 8) * 40 + k0);
        qfl[ks][2] = *(const uint32_t*)(sql + (mrow + r) * 40 + k0 + 8);
        qfl[ks][3] = *(const uint32_t*)(sql + (mrow + r + 8) * 40 + k0 + 8);
    }

    // ldmatrix lane-invariant address pieces
    const uint32_t skh_u = smem_u32(skh);
    const uint32_t skl_u = smem_u32(skl);
    const uint32_t k_laneoff = ((uint32_t)(lane & 7) * 20u + (uint32_t)(lane >> 3) * 4u) * 4u;
    const uint32_t sv_base = (lane < 16) ? smem_u32(svh) : smem_u32(svl);
    const uint32_t v_laneoff = ((uint32_t)(lane & 7) * 292u + (uint32_t)((lane >> 3) & 1) * 4u) * 4u;

    float O[4][4] = {};
    float rs0 = 0.f, rs1 = 0.f;

    for (int chunk = 0; chunk < 9; ++chunk) {
        const int n0 = chunk * 64;
        float S[8][4];
#pragma unroll
        for (int nb = 0; nb < 8; ++nb)
#pragma unroll
            for (int i = 0; i < 4; ++i) S[nb][i] = 0.f;

        // S = Qh*Kh + Qh*Kl + Ql*Kh
#pragma unroll
        for (int nb = 0; nb < 8; ++nb) {
            const uint32_t rowoff = (uint32_t)(n0 + nb * 8) * 80u;
            uint32_t h0, h1, h2, h3, l0, l1, l2, l3;
            ldsm_x4(h0, h1, h2, h3, skh_u + k_laneoff + rowoff);
            ldsm_x4(l0, l1, l2, l3, skl_u + k_laneoff + rowoff);
            uint32_t bh0[2] = {h0, h1}, bh1[2] = {h2, h3};
            uint32_t bl0[2] = {l0, l1}, bl1[2] = {l2, l3};
            mma16816(S[nb], qfh[0], bh0, S[nb]);
            mma16816(S[nb], qfh[1], bh1, S[nb]);
            mma16816(S[nb], qfh[0], bl0, S[nb]);
            mma16816(S[nb], qfh[1], bl1, S[nb]);
            mma16816(S[nb], qfl[0], bh0, S[nb]);
            mma16816(S[nb], qfl[1], bh1, S[nb]);
        }

        // exp (no-max softmax; logits bounded) + PV per 16-k window
#pragma unroll
        for (int j = 0; j < 4; ++j) {
            float e[8];
#pragma unroll
            for (int i = 0; i < 4; ++i) {
                e[i]     = __expf(S[2 * j][i]     * ATTN_SCALE);
                e[4 + i] = __expf(S[2 * j + 1][i] * ATTN_SCALE);
            }
            rs0 += e[0] + e[1] + e[4] + e[5];
            rs1 += e[2] + e[3] + e[6] + e[7];

            uint32_t ph[4], pl[4];
#pragma unroll
            for (int i = 0; i < 4; ++i) {
                float a = e[2 * i], bb = e[2 * i + 1];
                uint32_t hp = pack_bf16(a, bb);
                float ra = a  - __uint_as_float(hp << 16);
                float rb = bb - __uint_as_float(hp & 0xffff0000u);
                ph[i] = hp;
                pl[i] = pack_bf16(ra, rb);
            }

            const uint32_t jbase = (uint32_t)(n0 / 2 + j * 8) * 4u;
#pragma unroll
            for (int dhb = 0; dhb < 4; ++dhb) {
                uint32_t m0r, m1r, m2r, m3r;
                ldsm_x4(m0r, m1r, m2r, m3r,
                        sv_base + v_laneoff + (uint32_t)dhb * (8u * 292u * 4u) + jbase);
                uint32_t bh2[2] = {m0r, m1r}, bl2[2] = {m2r, m3r};
                mma16816(O[dhb], ph, bh2, O[dhb]);
                mma16816(O[dhb], ph, bl2, O[dhb]);
                mma16816(O[dhb], pl, bh2, O[dhb]);
            }
        }
    }

    // ---- rowsum reduce over 4 lanes of each row group ----
    rs0 += __shfl_xor_sync(0xffffffffu, rs0, 1);
    rs0 += __shfl_xor_sync(0xffffffffu, rs0, 2);
    rs1 += __shfl_xor_sync(0xffffffffu, rs1, 1);
    rs1 += __shfl_xor_sync(0xffffffffu, rs1, 2);
    float inv0 = 1.f / rs0, inv1 = 1.f / rs1;

    // ---- normalize + transpose via smem + coalesced store ----
    __syncthreads();
#pragma unroll
    for (int dhb = 0; dhb < 4; ++dhb) {
        int dh0 = dhb * 8 + c * 2;
        ostg[dh0 * 132 + mrow + r]           = O[dhb][0] * inv0;
        ostg[(dh0 + 1) * 132 + mrow + r]     = O[dhb][1] * inv0;
        ostg[dh0 * 132 + mrow + r + 8]       = O[dhb][2] * inv1;
        ostg[(dh0 + 1) * 132 + mrow + r + 8] = O[dhb][3] * inv1;
    }
    __syncthreads();
    float* ob = out + (size_t)(b * DIMC + h * DH) * HW + m0;
    for (int i = tid; i < 4096; i += 256) {
        int dh = i >> 7, m = i & 127;
        ob[(size_t)dh * HW + m] = ostg[dh * 132 + m];
    }
}

// ==================== launch ====================
extern "C" void kernel_launch(void* const* d_in, const int* in_sizes, int n_in,
                              void* d_out, int out_size)
{
    (void)in_sizes; (void)n_in; (void)out_size;
    const float* x    = (const float*)d_in[0];
    const float* kv   = (const float*)d_in[1];
    const float* wq   = (const float*)d_in[2];
    const float* bq   = (const float*)d_in[3];
    const float* wk   = (const float*)d_in[4];
    const float* bk   = (const float*)d_in[5];
    const float* wv   = (const float*)d_in[6];
    const float* bv   = (const float*)d_in[7];
    const float* wdw  = (const float*)d_in[8];
    const float* bdw  = (const float*)d_in[9];
    const float* lnw  = (const float*)d_in[10];
    const float* lnb  = (const float*)d_in[11];
    const float* woff = (const float*)d_in[12];
    const float* wo   = (const float*)d_in[13];
    const float* bo   = (const float*)d_in[14];
    float* out = (float*)d_out;

    float *q, *kvs, *ao;
    __nv_bfloat16 *kthi, *ktlo, *vhi, *vlo;
    cudaGetSymbolAddress((void**)&q,    g_q);
    cudaGetSymbolAddress((void**)&kvs,  g_kvs);
    cudaGetSymbolAddress((void**)&ao,   g_ao);
    cudaGetSymbolAddress((void**)&kthi, g_kthi);
    cudaGetSymbolAddress((void**)&ktlo, g_ktlo);
    cudaGetSymbolAddress((void**)&vhi,  g_vhi);
    cudaGetSymbolAddress((void**)&vlo,  g_vlo);

    cudaFuncSetAttribute(attn_mma_kernel, cudaFuncAttributeMaxDynamicSharedMemorySize, A_SMEM);

    // 1) q projection
    gemm_bias_kernel<<<dim3(HW / 64, DIMC / 64, BATCH), 256>>>(wq, x, bq, q, HW);
    // 2) depthwise + LN + GELU + offsets + bilinear sample
    offset_sample_kernel<<<(64 * NKS) / 8, 256>>>(q, kv, wdw, bdw, lnw, lnb, woff, kvs);
    // 3) fused k+v projections with bf16 split epilogue
    gemm_kv_kernel<<<dim3(NKS / 64, 8, BATCH), 256>>>(wk, bk, wv, bv, kvs, kthi, ktlo, vhi, vlo);
    // 4) attention (mma.sync + ldmatrix)
    attn_mma_kernel<<<dim3(HW / 128, 64), 256, A_SMEM>>>(
        q, (const uint32_t*)kthi, (const uint32_t*)ktlo,
        (const uint32_t*)vhi, (const uint32_t*)vlo, ao);
    // 5) output projection
    gemm_bias_kernel<<<dim3(HW / 64, DIMC / 64, BATCH), 256>>>(wo, ao, bo, out, HW);
}

// round 6
// speedup vs baseline: 1.9922x; 1.1757x over previous
#include <cuda_runtime.h>
#include <cuda_bf16.h>
#include <math.h>
#include <stdint.h>

#define BATCH 8
#define DIMC  256
#define HH    48
#define WWD   48
#define HW    2304
#define HEADS 8
#define DH    32
#define HKD   24
#define NKS   576
#define ATTN_SCALE 0.17677669529663687f

// ==================== scratch (device globals) ====================
__device__ float g_q  [BATCH * DIMC * HW];
__device__ float g_kvs[BATCH * DIMC * NKS];
__device__ float g_ao [BATCH * DIMC * HW];
__device__ __nv_bfloat16 g_kthi[64 * NKS * DH];   // [bh][n][dh]
__device__ __nv_bfloat16 g_ktlo[64 * NKS * DH];
__device__ __nv_bfloat16 g_vhi [64 * DH * NKS];   // [bh][dh][n]
__device__ __nv_bfloat16 g_vlo [64 * DH * NKS];

// ==================== helpers ====================
__device__ __forceinline__ float warp_sum(float v) {
#pragma unroll
    for (int o = 16; o; o >>= 1) v += __shfl_xor_sync(0xffffffffu, v, o);
    return v;
}
__device__ __forceinline__ uint32_t smem_u32(const void* p) {
    uint32_t a;
    asm("{ .reg .u64 t; cvta.to.shared.u64 t, %1; cvt.u32.u64 %0, t; }" : "=r"(a) : "l"(p));
    return a;
}
__device__ __forceinline__ uint32_t pack_bf16(float a, float b) {
    uint32_t r;
    asm("cvt.rn.satfinite.bf16x2.f32 %0, %1, %2;" : "=r"(r) : "f"(b), "f"(a));
    return r;
}
__device__ __forceinline__ void mma16816(float* d, const uint32_t* a, const uint32_t* b,
                                         const float* c) {
    asm volatile("mma.sync.aligned.m16n8k16.row.col.f32.bf16.bf16.f32 "
        "{%0,%1,%2,%3}, {%4,%5,%6,%7}, {%8,%9}, {%10,%11,%12,%13};"
        : "=f"(d[0]), "=f"(d[1]), "=f"(d[2]), "=f"(d[3])
        : "r"(a[0]), "r"(a[1]), "r"(a[2]), "r"(a[3]),
          "r"(b[0]), "r"(b[1]),
          "f"(c[0]), "f"(c[1]), "f"(c[2]), "f"(c[3]));
}
__device__ __forceinline__ void ldsm_x4(uint32_t& r0, uint32_t& r1, uint32_t& r2,
                                        uint32_t& r3, uint32_t addr) {
    asm volatile("ldmatrix.sync.aligned.m8n8.x4.shared.b16 {%0,%1,%2,%3}, [%4];"
                 : "=r"(r0), "=r"(r1), "=r"(r2), "=r"(r3) : "r"(addr));
}
__device__ __forceinline__ void cp16(uint32_t saddr, const void* g) {
    asm volatile("cp.async.cg.shared.global [%0], [%1], 16;" :: "r"(saddr), "l"(g));
}
#define CP_COMMIT() asm volatile("cp.async.commit_group;" ::: "memory")
#define CP_WAIT1()  asm volatile("cp.async.wait_group 1;" ::: "memory")
#define CP_WAIT0()  asm volatile("cp.async.wait_group 0;" ::: "memory")

// ==================== batched GEMM (fp32): q and o projections ====================
__global__ void gemm_bias_kernel(const float* __restrict__ W,
                                 const float* __restrict__ X,
                                 const float* __restrict__ bias,
                                 float* __restrict__ C, int N)
{
    __shared__ float As[16][64];
    __shared__ float Bs[16][64];
    const int n0 = blockIdx.x * 64;
    const int m0 = blockIdx.y * 64;
    X += (size_t)blockIdx.z * DIMC * N;
    C += (size_t)blockIdx.z * DIMC * N;
    const int tid = threadIdx.x;
    const int tx = tid & 15, ty = tid >> 4;
    float acc[4][4] = {};
    for (int k0 = 0; k0 < DIMC; k0 += 16) {
        {
            int mm = tid >> 2, kq = tid & 3;
            float4 a = *(const float4*)(W + (size_t)(m0 + mm) * DIMC + k0 + kq * 4);
            As[kq * 4 + 0][mm] = a.x; As[kq * 4 + 1][mm] = a.y;
            As[kq * 4 + 2][mm] = a.z; As[kq * 4 + 3][mm] = a.w;
        }
        {
            int r = tid >> 4, cq = tid & 15;
            *(float4*)(&Bs[r][cq * 4]) = *(const float4*)(X + (size_t)(k0 + r) * N + n0 + cq * 4);
        }
        __syncthreads();
#pragma unroll
        for (int kk = 0; kk < 16; ++kk) {
            float4 a = *(const float4*)(&As[kk][ty * 4]);
            float4 b = *(const float4*)(&Bs[kk][tx * 4]);
            float av[4] = {a.x, a.y, a.z, a.w};
            float bv[4] = {b.x, b.y, b.z, b.w};
#pragma unroll
            for (int i = 0; i < 4; ++i)
#pragma unroll
                for (int j = 0; j < 4; ++j) acc[i][j] += av[i] * bv[j];
        }
        __syncthreads();
    }
#pragma unroll
    for (int i = 0; i < 4; ++i) {
        float bi = bias[m0 + ty * 4 + i];
        float4 o = make_float4(acc[i][0] + bi, acc[i][1] + bi, acc[i][2] + bi, acc[i][3] + bi);
        *(float4*)(C + (size_t)(m0 + ty * 4 + i) * N + n0 + tx * 4) = o;
    }
}

// ==================== fused k+v GEMM with bf16 hi/lo split epilogue ====================
__global__ void gemm_kv_kernel(const float* __restrict__ Wk, const float* __restrict__ bk,
                               const float* __restrict__ Wv, const float* __restrict__ bv,
                               const float* __restrict__ X,
                               __nv_bfloat16* __restrict__ kthi, __nv_bfloat16* __restrict__ ktlo,
                               __nv_bfloat16* __restrict__ vhi,  __nv_bfloat16* __restrict__ vlo)
{
    __shared__ float As[16][64];
    __shared__ float Bs[16][64];
    const int n0 = blockIdx.x * 64;
    const bool isV = blockIdx.y >= 4;
    const int m0 = (blockIdx.y & 3) * 64;
    const float* W  = isV ? Wv : Wk;
    const float* bb = isV ? bv : bk;
    X += (size_t)blockIdx.z * DIMC * NKS;
    const int tid = threadIdx.x;
    const int tx = tid & 15, ty = tid >> 4;
    float acc[4][4] = {};
    for (int k0 = 0; k0 < DIMC; k0 += 16) {
        {
            int mm = tid >> 2, kq = tid & 3;
            float4 a = *(const float4*)(W + (size_t)(m0 + mm) * DIMC + k0 + kq * 4);
            As[kq * 4 + 0][mm] = a.x; As[kq * 4 + 1][mm] = a.y;
            As[kq * 4 + 2][mm] = a.z; As[kq * 4 + 3][mm] = a.w;
        }
        {
            int r = tid >> 4, cq = tid & 15;
            *(float4*)(&Bs[r][cq * 4]) = *(const float4*)(X + (size_t)(k0 + r) * NKS + n0 + cq * 4);
        }
        __syncthreads();
#pragma unroll
        for (int kk = 0; kk < 16; ++kk) {
            float4 a = *(const float4*)(&As[kk][ty * 4]);
            float4 b = *(const float4*)(&Bs[kk][tx * 4]);
            float av[4] = {a.x, a.y, a.z, a.w};
            float bv2[4] = {b.x, b.y, b.z, b.w};
#pragma unroll
            for (int i = 0; i < 4; ++i)
#pragma unroll
                for (int j = 0; j < 4; ++j) acc[i][j] += av[i] * bv2[j];
        }
        __syncthreads();
    }
    const int mbase = m0 + ty * 4;
    const int h  = mbase >> 5;
    const int dh0 = mbase & 31;
    const int bh = blockIdx.z * 8 + h;
    float hi4[4][4], lo4[4][4];
#pragma unroll
    for (int i = 0; i < 4; ++i) {
        float bi = bb[mbase + i];
#pragma unroll
        for (int j = 0; j < 4; ++j) {
            float x = acc[i][j] + bi;
            float hv = __bfloat162float(__float2bfloat16(x));
            hi4[i][j] = hv;
            lo4[i][j] = x - hv;
        }
    }
    if (!isV) {
        __nv_bfloat16* oh = kthi + (size_t)bh * NKS * DH;
        __nv_bfloat16* ol = ktlo + (size_t)bh * NKS * DH;
#pragma unroll
        for (int j = 0; j < 4; ++j) {
            int n = n0 + tx * 4 + j;
            uint32_t p0 = pack_bf16(hi4[0][j], hi4[1][j]);
            uint32_t p1 = pack_bf16(hi4[2][j], hi4[3][j]);
            *(uint2*)(oh + (size_t)n * DH + dh0) = make_uint2(p0, p1);
            uint32_t q0 = pack_bf16(lo4[0][j], lo4[1][j]);
            uint32_t q1 = pack_bf16(lo4[2][j], lo4[3][j]);
            *(uint2*)(ol + (size_t)n * DH + dh0) = make_uint2(q0, q1);
        }
    } else {
        __nv_bfloat16* oh = vhi + (size_t)bh * DH * NKS;
        __nv_bfloat16* ol = vlo + (size_t)bh * DH * NKS;
#pragma unroll
        for (int i = 0; i < 4; ++i) {
            int n = n0 + tx * 4;
            uint32_t p0 = pack_bf16(hi4[i][0], hi4[i][1]);
            uint32_t p1 = pack_bf16(hi4[i][2], hi4[i][3]);
            *(uint2*)(oh + (size_t)(dh0 + i) * NKS + n) = make_uint2(p0, p1);
            uint32_t q0 = pack_bf16(lo4[i][0], lo4[i][1]);
            uint32_t q1 = pack_bf16(lo4[i][2], lo4[i][3]);
            *(uint2*)(ol + (size_t)(dh0 + i) * NKS + n) = make_uint2(q0, q1);
        }
    }
}

// ==================== offset + sample ====================
__global__ void offset_sample_kernel(const float* __restrict__ q,
                                     const float* __restrict__ kv,
                                     const float* __restrict__ w_dw,
                                     const float* __restrict__ b_dw,
                                     const float* __restrict__ ln_w,
                                     const float* __restrict__ ln_b,
                                     const float* __restrict__ w_off,
                                     float* __restrict__ kvs)
{
    __shared__ float s_wdw[32 * 25];
    __shared__ float s_bdw[32], s_lnw[32], s_lnb[32], s_woff[64];
    const int tid = threadIdx.x;
    for (int i = tid; i < 800; i += 256) s_wdw[i] = w_dw[i];
    if (tid < 32) { s_bdw[tid] = b_dw[tid]; s_lnw[tid] = ln_w[tid]; s_lnb[tid] = ln_b[tid]; }
    if (tid < 64) s_woff[tid] = w_off[tid];
    __syncthreads();
    const int wid  = blockIdx.x * 8 + (tid >> 5);
    const int lane = tid & 31;
    const int bh  = wid / NKS;
    const int pos = wid - bh * NKS;
    const int hk  = pos / HKD;
    const int wk  = pos - hk * HKD;
    const int b   = bh >> 3;
    const int h   = bh & 7;
    const float* qc = q + ((size_t)(b * DIMC + h * DH + lane)) * HW;
    float t = 0.f;
    const int y0 = hk * 2 - 2, x0 = wk * 2 - 2;
#pragma unroll
    for (int i = 0; i < 5; ++i) {
        int yy = y0 + i;
        if ((unsigned)yy < (unsigned)HH) {
#pragma unroll
            for (int j = 0; j < 5; ++j) {
                int xx = x0 + j;
                if ((unsigned)xx < (unsigned)WWD)
                    t += qc[yy * WWD + xx] * s_wdw[lane * 25 + i * 5 + j];
            }
        }
    }
    t += s_bdw[lane];
    float mu  = warp_sum(t) * (1.f / 32.f);
    float d   = t - mu;
    float var = warp_sum(d * d) * (1.f / 32.f);
    t = d * rsqrtf(var + 1e-5f) * s_lnw[lane] + s_lnb[lane];
    t = 0.5f * t * (1.f + erff(t * 0.70710678118654752f));
    float o0 = warp_sum(s_woff[lane] * t);
    float o1 = warp_sum(s_woff[32 + lane] * t);
    const float refy = (0.5f + (float)hk) * (2.f / 23.f) - 1.f;
    const float refx = (0.5f + (float)wk) * (2.f / 23.f) - 1.f;
    float py = fminf(fmaxf(o0 + refy, -1.f), 1.f);
    float px = fminf(fmaxf(o1 + refx, -1.f), 1.f);
    float gx = (px + 1.f) * 0.5f * 47.f;
    float gy = (py + 1.f) * 0.5f * 47.f;
    float fx = floorf(gx), fy = floorf(gy);
    float wx = gx - fx,   wy = gy - fy;
    int x0i = min(max((int)fx, 0), 47);
    int x1i = min(max((int)fx + 1, 0), 47);
    int y0i = min(max((int)fy, 0), 47);
    int y1i = min(max((int)fy + 1, 0), 47);
    const float* kvc = kv + ((size_t)(b * DIMC + h * DH + lane)) * HW;
    float v00 = kvc[y0i * WWD + x0i];
    float v01 = kvc[y0i * WWD + x1i];
    float v10 = kvc[y1i * WWD + x0i];
    float v11 = kvc[y1i * WWD + x1i];
    float val = (1.f - wx) * (1.f - wy) * v00 + wx * (1.f - wy) * v01 +
                (1.f - wx) * wy * v10 + wx * wy * v11;
    kvs[((size_t)(b * DIMC + h * DH + lane)) * NKS + pos] = val;
}

// ==================== streamed mma.sync attention ====================
// grid (18, 64), 256 threads. K/V streamed in 64-n chunks, double buffered cp.async.
// per-buffer: Khi[64][20w]@0 (5120B) Klo@5120 Vhi[32][36w]@10240 (4608B) Vlo@14848; size 19456
#define BUF_SZ  19456
#define A_QSTG  38912           // sqh [128][40] bf16 (10240B), sql +10240
#define A_SMEM  59392

__global__ void __launch_bounds__(256)
attn_mma_kernel(const float* __restrict__ q,
                const uint32_t* __restrict__ kthi, const uint32_t* __restrict__ ktlo,
                const uint32_t* __restrict__ vhi,  const uint32_t* __restrict__ vlo,
                float* __restrict__ out)
{
    extern __shared__ char smem[];
    const uint32_t sb = smem_u32(smem);
    __nv_bfloat16* sqh = (__nv_bfloat16*)(smem + A_QSTG);
    __nv_bfloat16* sql = (__nv_bfloat16*)(smem + A_QSTG + 10240);
    float* ostg = (float*)(smem + A_QSTG);   // [32][132] f32 (reuse after loop)

    const int tid  = threadIdx.x;
    const int lane = tid & 31, warp = tid >> 5;
    const int bh = blockIdx.y, b = bh >> 3, h = bh & 7;
    const int m0 = blockIdx.x * 128;

    const uint32_t* gkh = kthi + (size_t)bh * 9216;
    const uint32_t* gkl = ktlo + (size_t)bh * 9216;
    const uint32_t* gvh = vhi + (size_t)bh * 9216;
    const uint32_t* gvl = vlo + (size_t)bh * 9216;

    // prefetch chunk c (64 n values) into buffer buf.
    // 1024 x 16B segments: [0,256) Khi, [256,512) Klo, [512,768) Vhi, [768,1024) Vlo
    auto prefetch = [&](int c, int buf) {
        const uint32_t bb = sb + buf * BUF_SZ;
#pragma unroll
        for (int s = tid; s < 1024; s += 256) {
            if (s < 256) {                       // K hi: n = s>>2, 4 segs/n
                int n = s >> 2, p = s & 3;
                cp16(bb + n * 80 + p * 16, gkh + c * 1024 + s * 4);
            } else if (s < 512) {                // K lo
                int t = s - 256, n = t >> 2, p = t & 3;
                cp16(bb + 5120 + n * 80 + p * 16, gkl + c * 1024 + t * 4);
            } else if (s < 768) {                // V hi: dh = t>>3, 8 segs/dh
                int t = s - 512, dh = t >> 3, p = t & 7;
                cp16(bb + 10240 + dh * 144 + p * 16, gvh + dh * 288 + c * 32 + p * 4);
            } else {                             // V lo
                int t = s - 768, dh = t >> 3, p = t & 7;
                cp16(bb + 14848 + dh * 144 + p * 16, gvl + dh * 288 + c * 32 + p * 4);
            }
        }
        CP_COMMIT();
    };

    prefetch(0, 0);

    // ---- Q tile: fp32 -> bf16 hi/lo staged [m][dh] ----
    const float* qb = q + (size_t)(b * DIMC + h * DH) * HW + m0;
    for (int i = tid; i < 4096; i += 256) {
        int dh = i >> 7, m = i & 127;
        float x = qb[(size_t)dh * HW + m];
        __nv_bfloat16 hi = __float2bfloat16(x);
        float lo = x - __bfloat162float(hi);
        sqh[m * 40 + dh] = hi;
        sql[m * 40 + dh] = __float2bfloat16(lo);
    }
    __syncthreads();

    // ---- Q fragments ----
    const int r = lane >> 2, c2 = lane & 3;
    const int mrow = warp * 16;
    uint32_t qfh[2][4], qfl[2][4];
#pragma unroll
    for (int ks = 0; ks < 2; ++ks) {
        int k0 = ks * 16 + c2 * 2;
        qfh[ks][0] = *(const uint32_t*)(sqh + (mrow + r) * 40 + k0);
        qfh[ks][1] = *(const uint32_t*)(sqh + (mrow + r + 8) * 40 + k0);
        qfh[ks][2] = *(const uint32_t*)(sqh + (mrow + r) * 40 + k0 + 8);
        qfh[ks][3] = *(const uint32_t*)(sqh + (mrow + r + 8) * 40 + k0 + 8);
        qfl[ks][0] = *(const uint32_t*)(sql + (mrow + r) * 40 + k0);
        qfl[ks][1] = *(const uint32_t*)(sql + (mrow + r + 8) * 40 + k0);
        qfl[ks][2] = *(const uint32_t*)(sql + (mrow + r) * 40 + k0 + 8);
        qfl[ks][3] = *(const uint32_t*)(sql + (mrow + r + 8) * 40 + k0 + 8);
    }

    const uint32_t k_laneoff = ((uint32_t)(lane & 7) * 20u + (uint32_t)(lane >> 3) * 4u) * 4u;
    const uint32_t v_laneoff = ((uint32_t)(lane & 7) * 36u + (uint32_t)((lane >> 3) & 1) * 4u) * 4u;
    const uint32_t v_hl = (lane < 16) ? 10240u : 14848u;

    float O[4][4] = {};
    float rs0 = 0.f, rs1 = 0.f;

    for (int chunk = 0; chunk < 9; ++chunk) {
        if (chunk < 8) { prefetch(chunk + 1, (chunk + 1) & 1); CP_WAIT1(); }
        else           { CP_WAIT0(); }
        __syncthreads();

        const uint32_t bufb = sb + (chunk & 1) * BUF_SZ;
        float S[8][4];
#pragma unroll
        for (int nb = 0; nb < 8; ++nb)
#pragma unroll
            for (int i = 0; i < 4; ++i) S[nb][i] = 0.f;

        // S = Qh*Kh + Qh*Kl + Ql*Kh
#pragma unroll
        for (int nb = 0; nb < 8; ++nb) {
            uint32_t h0, h1, h2, h3, l0, l1, l2, l3;
            ldsm_x4(h0, h1, h2, h3, bufb + k_laneoff + (uint32_t)nb * 640u);
            ldsm_x4(l0, l1, l2, l3, bufb + 5120u + k_laneoff + (uint32_t)nb * 640u);
            uint32_t bh0[2] = {h0, h1}, bh1[2] = {h2, h3};
            uint32_t bl0[2] = {l0, l1}, bl1[2] = {l2, l3};
            mma16816(S[nb], qfh[0], bh0, S[nb]);
            mma16816(S[nb], qfh[1], bh1, S[nb]);
            mma16816(S[nb], qfh[0], bl0, S[nb]);
            mma16816(S[nb], qfh[1], bl1, S[nb]);
            mma16816(S[nb], qfl[0], bh0, S[nb]);
            mma16816(S[nb], qfl[1], bh1, S[nb]);
        }

        // exp + PV per 16-n window
#pragma unroll
        for (int j = 0; j < 4; ++j) {
            float e[8];
#pragma unroll
            for (int i = 0; i < 4; ++i) {
                e[i]     = __expf(S[2 * j][i]     * ATTN_SCALE);
                e[4 + i] = __expf(S[2 * j + 1][i] * ATTN_SCALE);
            }
            rs0 += e[0] + e[1] + e[4] + e[5];
            rs1 += e[2] + e[3] + e[6] + e[7];

            uint32_t ph[4], pl[4];
#pragma unroll
            for (int i = 0; i < 4; ++i) {
                float a = e[2 * i], bb2 = e[2 * i + 1];
                uint32_t hp = pack_bf16(a, bb2);
                float ra = a   - __uint_as_float(hp << 16);
                float rb = bb2 - __uint_as_float(hp & 0xffff0000u);
                ph[i] = hp;
                pl[i] = pack_bf16(ra, rb);
            }

#pragma unroll
            for (int dhb = 0; dhb < 4; ++dhb) {
                uint32_t m0r, m1r, m2r, m3r;
                ldsm_x4(m0r, m1r, m2r, m3r,
                        bufb + v_hl + v_laneoff + (uint32_t)dhb * 1152u + (uint32_t)j * 32u);
                uint32_t bh2[2] = {m0r, m1r}, bl2[2] = {m2r, m3r};
                mma16816(O[dhb], ph, bh2, O[dhb]);
                mma16816(O[dhb], ph, bl2, O[dhb]);
                mma16816(O[dhb], pl, bh2, O[dhb]);
            }
        }
        __syncthreads();   // all warps done with this buffer before it's refilled
    }

    // ---- rowsum reduce ----
    rs0 += __shfl_xor_sync(0xffffffffu, rs0, 1);
    rs0 += __shfl_xor_sync(0xffffffffu, rs0, 2);
    rs1 += __shfl_xor_sync(0xffffffffu, rs1, 1);
    rs1 += __shfl_xor_sync(0xffffffffu, rs1, 2);
    float inv0 = 1.f / rs0, inv1 = 1.f / rs1;

    // ---- normalize + transpose via smem + coalesced store ----
    __syncthreads();
#pragma unroll
    for (int dhb = 0; dhb < 4; ++dhb) {
        int dh0 = dhb * 8 + c2 * 2;
        ostg[dh0 * 132 + mrow + r]           = O[dhb][0] * inv0;
        ostg[(dh0 + 1) * 132 + mrow + r]     = O[dhb][1] * inv0;
        ostg[dh0 * 132 + mrow + r + 8]       = O[dhb][2] * inv1;
        ostg[(dh0 + 1) * 132 + mrow + r + 8] = O[dhb][3] * inv1;
    }
    __syncthreads();
    float* ob = out + (size_t)(b * DIMC + h * DH) * HW + m0;
    for (int i = tid; i < 4096; i += 256) {
        int dh = i >> 7, m = i & 127;
        ob[(size_t)dh * HW + m] = ostg[dh * 132 + m];
    }
}

// ==================== launch ====================
extern "C" void kernel_launch(void* const* d_in, const int* in_sizes, int n_in,
                              void* d_out, int out_size)
{
    (void)in_sizes; (void)n_in; (void)out_size;
    const float* x    = (const float*)d_in[0];
    const float* kv   = (const float*)d_in[1];
    const float* wq   = (const float*)d_in[2];
    const float* bq   = (const float*)d_in[3];
    const float* wk   = (const float*)d_in[4];
    const float* bk   = (const float*)d_in[5];
    const float* wv   = (const float*)d_in[6];
    const float* bv   = (const float*)d_in[7];
    const float* wdw  = (const float*)d_in[8];
    const float* bdw  = (const float*)d_in[9];
    const float* lnw  = (const float*)d_in[10];
    const float* lnb  = (const float*)d_in[11];
    const float* woff = (const float*)d_in[12];
    const float* wo   = (const float*)d_in[13];
    const float* bo   = (const float*)d_in[14];
    float* out = (float*)d_out;

    float *q, *kvs, *ao;
    __nv_bfloat16 *kthi, *ktlo, *vhi, *vlo;
    cudaGetSymbolAddress((void**)&q,    g_q);
    cudaGetSymbolAddress((void**)&kvs,  g_kvs);
    cudaGetSymbolAddress((void**)&ao,   g_ao);
    cudaGetSymbolAddress((void**)&kthi, g_kthi);
    cudaGetSymbolAddress((void**)&ktlo, g_ktlo);
    cudaGetSymbolAddress((void**)&vhi,  g_vhi);
    cudaGetSymbolAddress((void**)&vlo,  g_vlo);

    cudaFuncSetAttribute(attn_mma_kernel, cudaFuncAttributeMaxDynamicSharedMemorySize, A_SMEM);

    // 1) q projection
    gemm_bias_kernel<<<dim3(HW / 64, DIMC / 64, BATCH), 256>>>(wq, x, bq, q, HW);
    // 2) depthwise + LN + GELU + offsets + bilinear sample
    offset_sample_kernel<<<(64 * NKS) / 8, 256>>>(q, kv, wdw, bdw, lnw, lnb, woff, kvs);
    // 3) fused k+v projections with bf16 split epilogue
    gemm_kv_kernel<<<dim3(NKS / 64, 8, BATCH), 256>>>(wk, bk, wv, bv, kvs, kthi, ktlo, vhi, vlo);
    // 4) attention (streamed cp.async + mma.sync + ldmatrix)
    attn_mma_kernel<<<dim3(HW / 128, 64), 256, A_SMEM>>>(
        q, (const uint32_t*)kthi, (const uint32_t*)ktlo,
        (const uint32_t*)vhi, (const uint32_t*)vlo, ao);
    // 5) output projection
    gemm_bias_kernel<<<dim3(HW / 64, DIMC / 64, BATCH), 256>>>(wo, ao, bo, out, HW);
}

// round 7
// speedup vs baseline: 2.3797x; 1.1945x over previous
#include <cuda_runtime.h>
#include <cuda_bf16.h>
#include <math.h>
#include <stdint.h>

#define BATCH 8
#define DIMC  256
#define HH    48
#define WWD   48
#define HW    2304
#define HEADS 8
#define DH    32
#define HKD   24
#define NKS   576
#define ATTN_SCALE 0.17677669529663687f

// ==================== scratch (device globals) ====================
__device__ float g_q  [BATCH * DIMC * HW];
__device__ float g_kvs[BATCH * DIMC * NKS];
__device__ __nv_bfloat16 g_kthi[64 * NKS * DH];
__device__ __nv_bfloat16 g_ktlo[64 * NKS * DH];
__device__ __nv_bfloat16 g_vhi [64 * DH * NKS];
__device__ __nv_bfloat16 g_vlo [64 * DH * NKS];
// split weights
__device__ __nv_bfloat16 g_wqhi[DIMC * DIMC], g_wqlo[DIMC * DIMC];
__device__ __nv_bfloat16 g_wohi[DIMC * DIMC], g_wolo[DIMC * DIMC];
// transposed split activations: [b][n][k]
__device__ __nv_bfloat16 g_xthi[BATCH * HW * DIMC], g_xtlo[BATCH * HW * DIMC];
__device__ __nv_bfloat16 g_aothi[BATCH * HW * DIMC], g_aotlo[BATCH * HW * DIMC];

// ==================== helpers ====================
__device__ __forceinline__ float warp_sum(float v) {
#pragma unroll
    for (int o = 16; o; o >>= 1) v += __shfl_xor_sync(0xffffffffu, v, o);
    return v;
}
__device__ __forceinline__ uint32_t smem_u32(const void* p) {
    uint32_t a;
    asm("{ .reg .u64 t; cvta.to.shared.u64 t, %1; cvt.u32.u64 %0, t; }" : "=r"(a) : "l"(p));
    return a;
}
__device__ __forceinline__ uint32_t pack_bf16(float a, float b) {
    uint32_t r;
    asm("cvt.rn.satfinite.bf16x2.f32 %0, %1, %2;" : "=r"(r) : "f"(b), "f"(a));
    return r;
}
__device__ __forceinline__ void mma16816(float* d, const uint32_t* a, const uint32_t* b,
                                         const float* c) {
    asm volatile("mma.sync.aligned.m16n8k16.row.col.f32.bf16.bf16.f32 "
        "{%0,%1,%2,%3}, {%4,%5,%6,%7}, {%8,%9}, {%10,%11,%12,%13};"
        : "=f"(d[0]), "=f"(d[1]), "=f"(d[2]), "=f"(d[3])
        : "r"(a[0]), "r"(a[1]), "r"(a[2]), "r"(a[3]),
          "r"(b[0]), "r"(b[1]),
          "f"(c[0]), "f"(c[1]), "f"(c[2]), "f"(c[3]));
}
__device__ __forceinline__ void ldsm_x4(uint32_t& r0, uint32_t& r1, uint32_t& r2,
                                        uint32_t& r3, uint32_t addr) {
    asm volatile("ldmatrix.sync.aligned.m8n8.x4.shared.b16 {%0,%1,%2,%3}, [%4];"
                 : "=r"(r0), "=r"(r1), "=r"(r2), "=r"(r3) : "r"(addr));
}
__device__ __forceinline__ void cp16(uint32_t saddr, const void* g) {
    asm volatile("cp.async.cg.shared.global [%0], [%1], 16;" :: "r"(saddr), "l"(g));
}
#define CP_COMMIT() asm volatile("cp.async.commit_group;" ::: "memory")
#define CP_WAIT1()  asm volatile("cp.async.wait_group 1;" ::: "memory")
#define CP_WAIT0()  asm volatile("cp.async.wait_group 0;" ::: "memory")

// ==================== weight split ====================
__global__ void split_w_kernel(const float* __restrict__ wq, const float* __restrict__ wo,
                               __nv_bfloat16* __restrict__ wqhi, __nv_bfloat16* __restrict__ wqlo,
                               __nv_bfloat16* __restrict__ wohi, __nv_bfloat16* __restrict__ wolo)
{
    int i = blockIdx.x * 512 + threadIdx.x;
    float x;
    __nv_bfloat16 hi;
    if (i < 65536) {
        x = wq[i]; hi = __float2bfloat16(x);
        wqhi[i] = hi; wqlo[i] = __float2bfloat16(x - __bfloat162float(hi));
    } else {
        int j = i - 65536;
        x = wo[j]; hi = __float2bfloat16(x);
        wohi[j] = hi; wolo[j] = __float2bfloat16(x - __bfloat162float(hi));
    }
}

// ==================== x transpose + split: x[b][k][n] -> xt[b][n][k] ====================
__global__ void split_x_kernel(const float* __restrict__ x,
                               __nv_bfloat16* __restrict__ xthi,
                               __nv_bfloat16* __restrict__ xtlo)
{
    __shared__ float tile[32][33];
    const int n0 = blockIdx.x * 32, c0 = blockIdx.y * 32, b = blockIdx.z;
    const int tid = threadIdx.x;
    for (int i = tid; i < 1024; i += 256) {
        int c = i >> 5, n = i & 31;
        tile[c][n] = x[((size_t)b * DIMC + c0 + c) * HW + n0 + n];
    }
    __syncthreads();
    for (int i = tid; i < 1024; i += 256) {
        int n = i >> 5, c = i & 31;
        float v = tile[c][n];
        __nv_bfloat16 hi = __float2bfloat16(v);
        size_t idx = ((size_t)b * HW + n0 + n) * DIMC + c0 + c;
        xthi[idx] = hi;
        xtlo[idx] = __float2bfloat16(v - __bfloat162float(hi));
    }
}

// ==================== tensor-core projection GEMM ====================
// C[b][m 256][n 2304] = W(256x256) @ X(256x2304) + bias, split-bf16 3-product emulation.
// grid (36, 2, 8), 256 threads. CTA tile m128 x n64, warps m32 x n32 (4x2).
// A = W[m][k] row-major hi/lo; B = Xt[n][k] hi/lo. K streamed in 8 chunks of 32.
#define G_BUF  30720   // Ahi[128][20w]=10240 @0, Alo @10240, Bhi[64][20w]=5120 @20480, Blo @25600
#define G_SMEM 61440

__global__ void __launch_bounds__(256)
gemm_tc_kernel(const uint32_t* __restrict__ whi, const uint32_t* __restrict__ wlo,
               const float* __restrict__ bias,
               const uint32_t* __restrict__ xthi, const uint32_t* __restrict__ xtlo,
               float* __restrict__ C)
{
    extern __shared__ char smem[];
    const uint32_t sb = smem_u32(smem);
    const int tid = threadIdx.x;
    const int lane = tid & 31, warp = tid >> 5;
    const int n0 = blockIdx.x * 64;
    const int m0 = blockIdx.y * 128;
    const int b  = blockIdx.z;

    const uint32_t* xh = xthi + (size_t)b * HW * (DIMC / 2);
    const uint32_t* xl = xtlo + (size_t)b * HW * (DIMC / 2);

    // prefetch chunk kc into buffer buf. 1536 x 16B segs:
    // [0,512) Ahi, [512,1024) Alo, [1024,1280) Bhi, [1280,1536) Blo
    auto prefetch = [&](int kc, int buf) {
        const uint32_t bb = sb + buf * G_BUF;
#pragma unroll
        for (int s = tid; s < 1536; s += 256) {
            if (s < 512) {
                int row = s >> 2, p = s & 3;
                cp16(bb + row * 80 + p * 16, whi + (size_t)(m0 + row) * 128 + kc * 16 + p * 4);
            } else if (s < 1024) {
                int t = s - 512, row = t >> 2, p = t & 3;
                cp16(bb + 10240 + row * 80 + p * 16, wlo + (size_t)(m0 + row) * 128 + kc * 16 + p * 4);
            } else if (s < 1280) {
                int t = s - 1024, row = t >> 2, p = t & 3;
                cp16(bb + 20480 + row * 80 + p * 16, xh + (size_t)(n0 + row) * 128 + kc * 16 + p * 4);
            } else {
                int t = s - 1280, row = t >> 2, p = t & 3;
                cp16(bb + 25600 + row * 80 + p * 16, xl + (size_t)(n0 + row) * 128 + kc * 16 + p * 4);
            }
        }
        CP_COMMIT();
    };

    prefetch(0, 0);

    const int warp_m = warp >> 1, warp_n = warp & 1;
    const int m_base = warp_m * 32, n_base = warp_n * 32;
    const uint32_t a_laneoff = (uint32_t)((lane & 15) * 80 + (lane >> 4) * 16);
    const uint32_t b_laneoff = (uint32_t)((lane & 7) * 80 + (lane >> 3) * 16);

    float acc[2][4][4] = {};

    for (int kc = 0; kc < 8; ++kc) {
        if (kc < 7) { prefetch(kc + 1, (kc + 1) & 1); CP_WAIT1(); }
        else        { CP_WAIT0(); }
        __syncthreads();
        const uint32_t bb = sb + (kc & 1) * G_BUF;

        // B fragments: 4 n-blocks of 8, each x4 covers k0-31
        uint32_t bfh[4][4], bfl[4][4];
#pragma unroll
        for (int nf = 0; nf < 4; ++nf) {
            uint32_t ad = bb + 20480u + (uint32_t)(n_base + nf * 8) * 80u + b_laneoff;
            ldsm_x4(bfh[nf][0], bfh[nf][1], bfh[nf][2], bfh[nf][3], ad);
            ldsm_x4(bfl[nf][0], bfl[nf][1], bfl[nf][2], bfl[nf][3], ad + 5120u);
        }
#pragma unroll
        for (int ks = 0; ks < 2; ++ks) {
#pragma unroll
            for (int mf = 0; mf < 2; ++mf) {
                uint32_t ad = bb + (uint32_t)(m_base + mf * 16) * 80u + a_laneoff + (uint32_t)ks * 32u;
                uint32_t ah[4], al[4];
                ldsm_x4(ah[0], ah[1], ah[2], ah[3], ad);
                ldsm_x4(al[0], al[1], al[2], al[3], ad + 10240u);
#pragma unroll
                for (int nf = 0; nf < 4; ++nf) {
                    uint32_t bh2[2] = { bfh[nf][ks * 2], bfh[nf][ks * 2 + 1] };
                    uint32_t bl2[2] = { bfl[nf][ks * 2], bfl[nf][ks * 2 + 1] };
                    mma16816(acc[mf][nf], ah, bh2, acc[mf][nf]);
                    mma16816(acc[mf][nf], ah, bl2, acc[mf][nf]);
                    mma16816(acc[mf][nf], al, bh2, acc[mf][nf]);
                }
            }
        }
        __syncthreads();
    }

    // epilogue: bias + fp32 store
    const int r = lane >> 2, c2 = lane & 3;
    float* Cb = C + (size_t)b * DIMC * HW;
#pragma unroll
    for (int mf = 0; mf < 2; ++mf) {
        int mrow = m0 + m_base + mf * 16;
        float b0 = bias[mrow + r], b1 = bias[mrow + r + 8];
#pragma unroll
        for (int nf = 0; nf < 4; ++nf) {
            int n = n0 + n_base + nf * 8 + c2 * 2;
            *(float2*)(Cb + (size_t)(mrow + r) * HW + n) =
                make_float2(acc[mf][nf][0] + b0, acc[mf][nf][1] + b0);
            *(float2*)(Cb + (size_t)(mrow + r + 8) * HW + n) =
                make_float2(acc[mf][nf][2] + b1, acc[mf][nf][3] + b1);
        }
    }
}

// ==================== fused k+v GEMM with bf16 hi/lo split epilogue (fp32 core) ====================
__global__ void gemm_kv_kernel(const float* __restrict__ Wk, const float* __restrict__ bk,
                               const float* __restrict__ Wv, const float* __restrict__ bv,
                               const float* __restrict__ X,
                               __nv_bfloat16* __restrict__ kthi, __nv_bfloat16* __restrict__ ktlo,
                               __nv_bfloat16* __restrict__ vhi,  __nv_bfloat16* __restrict__ vlo)
{
    __shared__ float As[16][64];
    __shared__ float Bs[16][64];
    const int n0 = blockIdx.x * 64;
    const bool isV = blockIdx.y >= 4;
    const int m0 = (blockIdx.y & 3) * 64;
    const float* W  = isV ? Wv : Wk;
    const float* bb = isV ? bv : bk;
    X += (size_t)blockIdx.z * DIMC * NKS;
    const int tid = threadIdx.x;
    const int tx = tid & 15, ty = tid >> 4;
    float acc[4][4] = {};
    for (int k0 = 0; k0 < DIMC; k0 += 16) {
        {
            int mm = tid >> 2, kq = tid & 3;
            float4 a = *(const float4*)(W + (size_t)(m0 + mm) * DIMC + k0 + kq * 4);
            As[kq * 4 + 0][mm] = a.x; As[kq * 4 + 1][mm] = a.y;
            As[kq * 4 + 2][mm] = a.z; As[kq * 4 + 3][mm] = a.w;
        }
        {
            int r = tid >> 4, cq = tid & 15;
            *(float4*)(&Bs[r][cq * 4]) = *(const float4*)(X + (size_t)(k0 + r) * NKS + n0 + cq * 4);
        }
        __syncthreads();
#pragma unroll
        for (int kk = 0; kk < 16; ++kk) {
            float4 a = *(const float4*)(&As[kk][ty * 4]);
            float4 b = *(const float4*)(&Bs[kk][tx * 4]);
            float av[4] = {a.x, a.y, a.z, a.w};
            float bv2[4] = {b.x, b.y, b.z, b.w};
#pragma unroll
            for (int i = 0; i < 4; ++i)
#pragma unroll
                for (int j = 0; j < 4; ++j) acc[i][j] += av[i] * bv2[j];
        }
        __syncthreads();
    }
    const int mbase = m0 + ty * 4;
    const int h  = mbase >> 5;
    const int dh0 = mbase & 31;
    const int bh = blockIdx.z * 8 + h;
    float hi4[4][4], lo4[4][4];
#pragma unroll
    for (int i = 0; i < 4; ++i) {
        float bi = bb[mbase + i];
#pragma unroll
        for (int j = 0; j < 4; ++j) {
            float x = acc[i][j] + bi;
            float hv = __bfloat162float(__float2bfloat16(x));
            hi4[i][j] = hv;
            lo4[i][j] = x - hv;
        }
    }
    if (!isV) {
        __nv_bfloat16* oh = kthi + (size_t)bh * NKS * DH;
        __nv_bfloat16* ol = ktlo + (size_t)bh * NKS * DH;
#pragma unroll
        for (int j = 0; j < 4; ++j) {
            int n = n0 + tx * 4 + j;
            *(uint2*)(oh + (size_t)n * DH + dh0) =
                make_uint2(pack_bf16(hi4[0][j], hi4[1][j]), pack_bf16(hi4[2][j], hi4[3][j]));
            *(uint2*)(ol + (size_t)n * DH + dh0) =
                make_uint2(pack_bf16(lo4[0][j], lo4[1][j]), pack_bf16(lo4[2][j], lo4[3][j]));
        }
    } else {
        __nv_bfloat16* oh = vhi + (size_t)bh * DH * NKS;
        __nv_bfloat16* ol = vlo + (size_t)bh * DH * NKS;
#pragma unroll
        for (int i = 0; i < 4; ++i) {
            int n = n0 + tx * 4;
            *(uint2*)(oh + (size_t)(dh0 + i) * NKS + n) =
                make_uint2(pack_bf16(hi4[i][0], hi4[i][1]), pack_bf16(hi4[i][2], hi4[i][3]));
            *(uint2*)(ol + (size_t)(dh0 + i) * NKS + n) =
                make_uint2(pack_bf16(lo4[i][0], lo4[i][1]), pack_bf16(lo4[i][2], lo4[i][3]));
        }
    }
}

// ==================== offset + sample ====================
__global__ void offset_sample_kernel(const float* __restrict__ q,
                                     const float* __restrict__ kv,
                                     const float* __restrict__ w_dw,
                                     const float* __restrict__ b_dw,
                                     const float* __restrict__ ln_w,
                                     const float* __restrict__ ln_b,
                                     const float* __restrict__ w_off,
                                     float* __restrict__ kvs)
{
    __shared__ float s_wdw[32 * 25];
    __shared__ float s_bdw[32], s_lnw[32], s_lnb[32], s_woff[64];
    const int tid = threadIdx.x;
    for (int i = tid; i < 800; i += 256) s_wdw[i] = w_dw[i];
    if (tid < 32) { s_bdw[tid] = b_dw[tid]; s_lnw[tid] = ln_w[tid]; s_lnb[tid] = ln_b[tid]; }
    if (tid < 64) s_woff[tid] = w_off[tid];
    __syncthreads();
    const int wid  = blockIdx.x * 8 + (tid >> 5);
    const int lane = tid & 31;
    const int bh  = wid / NKS;
    const int pos = wid - bh * NKS;
    const int hk  = pos / HKD;
    const int wk  = pos - hk * HKD;
    const int b   = bh >> 3;
    const int h   = bh & 7;
    const float* qc = q + ((size_t)(b * DIMC + h * DH + lane)) * HW;
    float t = 0.f;
    const int y0 = hk * 2 - 2, x0 = wk * 2 - 2;
#pragma unroll
    for (int i = 0; i < 5; ++i) {
        int yy = y0 + i;
        if ((unsigned)yy < (unsigned)HH) {
#pragma unroll
            for (int j = 0; j < 5; ++j) {
                int xx = x0 + j;
                if ((unsigned)xx < (unsigned)WWD)
                    t += qc[yy * WWD + xx] * s_wdw[lane * 25 + i * 5 + j];
            }
        }
    }
    t += s_bdw[lane];
    float mu  = warp_sum(t) * (1.f / 32.f);
    float d   = t - mu;
    float var = warp_sum(d * d) * (1.f / 32.f);
    t = d * rsqrtf(var + 1e-5f) * s_lnw[lane] + s_lnb[lane];
    t = 0.5f * t * (1.f + erff(t * 0.70710678118654752f));
    float o0 = warp_sum(s_woff[lane] * t);
    float o1 = warp_sum(s_woff[32 + lane] * t);
    const float refy = (0.5f + (float)hk) * (2.f / 23.f) - 1.f;
    const float refx = (0.5f + (float)wk) * (2.f / 23.f) - 1.f;
    float py = fminf(fmaxf(o0 + refy, -1.f), 1.f);
    float px = fminf(fmaxf(o1 + refx, -1.f), 1.f);
    float gx = (px + 1.f) * 0.5f * 47.f;
    float gy = (py + 1.f) * 0.5f * 47.f;
    float fx = floorf(gx), fy = floorf(gy);
    float wx = gx - fx,   wy = gy - fy;
    int x0i = min(max((int)fx, 0), 47);
    int x1i = min(max((int)fx + 1, 0), 47);
    int y0i = min(max((int)fy, 0), 47);
    int y1i = min(max((int)fy + 1, 0), 47);
    const float* kvc = kv + ((size_t)(b * DIMC + h * DH + lane)) * HW;
    float v00 = kvc[y0i * WWD + x0i];
    float v01 = kvc[y0i * WWD + x1i];
    float v10 = kvc[y1i * WWD + x0i];
    float v11 = kvc[y1i * WWD + x1i];
    float val = (1.f - wx) * (1.f - wy) * v00 + wx * (1.f - wy) * v01 +
                (1.f - wx) * wy * v10 + wx * wy * v11;
    kvs[((size_t)(b * DIMC + h * DH + lane)) * NKS + pos] = val;
}

// ==================== streamed mma.sync attention, split-bf16 transposed output ====================
#define BUF_SZ  19456
#define A_QSTG  38912
#define A_SMEM  59392

__global__ void __launch_bounds__(256)
attn_mma_kernel(const float* __restrict__ q,
                const uint32_t* __restrict__ kthi, const uint32_t* __restrict__ ktlo,
                const uint32_t* __restrict__ vhi,  const uint32_t* __restrict__ vlo,
                uint32_t* __restrict__ aothi, uint32_t* __restrict__ aotlo)
{
    extern __shared__ char smem[];
    const uint32_t sb = smem_u32(smem);
    __nv_bfloat16* sqh = (__nv_bfloat16*)(smem + A_QSTG);
    __nv_bfloat16* sql = (__nv_bfloat16*)(smem + A_QSTG + 10240);

    const int tid  = threadIdx.x;
    const int lane = tid & 31, warp = tid >> 5;
    const int bh = blockIdx.y, b = bh >> 3, h = bh & 7;
    const int m0 = blockIdx.x * 128;

    const uint32_t* gkh = kthi + (size_t)bh * 9216;
    const uint32_t* gkl = ktlo + (size_t)bh * 9216;
    const uint32_t* gvh = vhi + (size_t)bh * 9216;
    const uint32_t* gvl = vlo + (size_t)bh * 9216;

    auto prefetch = [&](int c, int buf) {
        const uint32_t bb = sb + buf * BUF_SZ;
#pragma unroll
        for (int s = tid; s < 1024; s += 256) {
            if (s < 256) {
                int n = s >> 2, p = s & 3;
                cp16(bb + n * 80 + p * 16, gkh + c * 1024 + s * 4);
            } else if (s < 512) {
                int t = s - 256, n = t >> 2, p = t & 3;
                cp16(bb + 5120 + n * 80 + p * 16, gkl + c * 1024 + t * 4);
            } else if (s < 768) {
                int t = s - 512, dh = t >> 3, p = t & 7;
                cp16(bb + 10240 + dh * 144 + p * 16, gvh + dh * 288 + c * 32 + p * 4);
            } else {
                int t = s - 768, dh = t >> 3, p = t & 7;
                cp16(bb + 14848 + dh * 144 + p * 16, gvl + dh * 288 + c * 32 + p * 4);
            }
        }
        CP_COMMIT();
    };

    prefetch(0, 0);

    const float* qb = q + (size_t)(b * DIMC + h * DH) * HW + m0;
    for (int i = tid; i < 4096; i += 256) {
        int dh = i >> 7, m = i & 127;
        float x = qb[(size_t)dh * HW + m];
        __nv_bfloat16 hi = __float2bfloat16(x);
        float lo = x - __bfloat162float(hi);
        sqh[m * 40 + dh] = hi;
        sql[m * 40 + dh] = __float2bfloat16(lo);
    }
    __syncthreads();

    const int r = lane >> 2, c2 = lane & 3;
    const int mrow = warp * 16;
    uint32_t qfh[2][4], qfl[2][4];
#pragma unroll
    for (int ks = 0; ks < 2; ++ks) {
        int k0 = ks * 16 + c2 * 2;
        qfh[ks][0] = *(const uint32_t*)(sqh + (mrow + r) * 40 + k0);
        qfh[ks][1] = *(const uint32_t*)(sqh + (mrow + r + 8) * 40 + k0);
        qfh[ks][2] = *(const uint32_t*)(sqh + (mrow + r) * 40 + k0 + 8);
        qfh[ks][3] = *(const uint32_t*)(sqh + (mrow + r + 8) * 40 + k0 + 8);
        qfl[ks][0] = *(const uint32_t*)(sql + (mrow + r) * 40 + k0);
        qfl[ks][1] = *(const uint32_t*)(sql + (mrow + r + 8) * 40 + k0);
        qfl[ks][2] = *(const uint32_t*)(sql + (mrow + r) * 40 + k0 + 8);
        qfl[ks][3] = *(const uint32_t*)(sql + (mrow + r + 8) * 40 + k0 + 8);
    }

    const uint32_t k_laneoff = ((uint32_t)(lane & 7) * 20u + (uint32_t)(lane >> 3) * 4u) * 4u;
    const uint32_t v_laneoff = ((uint32_t)(lane & 7) * 36u + (uint32_t)((lane >> 3) & 1) * 4u) * 4u;
    const uint32_t v_hl = (lane < 16) ? 10240u : 14848u;

    float O[4][4] = {};
    float rs0 = 0.f, rs1 = 0.f;

    for (int chunk = 0; chunk < 9; ++chunk) {
        if (chunk < 8) { prefetch(chunk + 1, (chunk + 1) & 1); CP_WAIT1(); }
        else           { CP_WAIT0(); }
        __syncthreads();

        const uint32_t bufb = sb + (chunk & 1) * BUF_SZ;
        float S[8][4];
#pragma unroll
        for (int nb = 0; nb < 8; ++nb)
#pragma unroll
            for (int i = 0; i < 4; ++i) S[nb][i] = 0.f;

#pragma unroll
        for (int nb = 0; nb < 8; ++nb) {
            uint32_t h0, h1, h2, h3, l0, l1, l2, l3;
            ldsm_x4(h0, h1, h2, h3, bufb + k_laneoff + (uint32_t)nb * 640u);
            ldsm_x4(l0, l1, l2, l3, bufb + 5120u + k_laneoff + (uint32_t)nb * 640u);
            uint32_t bh0[2] = {h0, h1}, bh1[2] = {h2, h3};
            uint32_t bl0[2] = {l0, l1}, bl1[2] = {l2, l3};
            mma16816(S[nb], qfh[0], bh0, S[nb]);
            mma16816(S[nb], qfh[1], bh1, S[nb]);
            mma16816(S[nb], qfh[0], bl0, S[nb]);
            mma16816(S[nb], qfh[1], bl1, S[nb]);
            mma16816(S[nb], qfl[0], bh0, S[nb]);
            mma16816(S[nb], qfl[1], bh1, S[nb]);
        }

#pragma unroll
        for (int j = 0; j < 4; ++j) {
            float e[8];
#pragma unroll
            for (int i = 0; i < 4; ++i) {
                e[i]     = __expf(S[2 * j][i]     * ATTN_SCALE);
                e[4 + i] = __expf(S[2 * j + 1][i] * ATTN_SCALE);
            }
            rs0 += e[0] + e[1] + e[4] + e[5];
            rs1 += e[2] + e[3] + e[6] + e[7];

            uint32_t ph[4], pl[4];
#pragma unroll
            for (int i = 0; i < 4; ++i) {
                float a = e[2 * i], bb2 = e[2 * i + 1];
                uint32_t hp = pack_bf16(a, bb2);
                float ra = a   - __uint_as_float(hp << 16);
                float rb = bb2 - __uint_as_float(hp & 0xffff0000u);
                ph[i] = hp;
                pl[i] = pack_bf16(ra, rb);
            }

#pragma unroll
            for (int dhb = 0; dhb < 4; ++dhb) {
                uint32_t m0r, m1r, m2r, m3r;
                ldsm_x4(m0r, m1r, m2r, m3r,
                        bufb + v_hl + v_laneoff + (uint32_t)dhb * 1152u + (uint32_t)j * 32u);
                uint32_t bh2[2] = {m0r, m1r}, bl2[2] = {m2r, m3r};
                mma16816(O[dhb], ph, bh2, O[dhb]);
                mma16816(O[dhb], ph, bl2, O[dhb]);
                mma16816(O[dhb], pl, bh2, O[dhb]);
            }
        }
        __syncthreads();
    }

    // rowsum reduce
    rs0 += __shfl_xor_sync(0xffffffffu, rs0, 1);
    rs0 += __shfl_xor_sync(0xffffffffu, rs0, 2);
    rs1 += __shfl_xor_sync(0xffffffffu, rs1, 1);
    rs1 += __shfl_xor_sync(0xffffffffu, rs1, 2);
    float inv0 = 1.f / rs0, inv1 = 1.f / rs1;

    // direct transposed split-bf16 output: aot[b][m][ch], ch = h*32 + dh
    // thread owns (m = mrow + r / r+8, dh = dhb*8 + 2c2, 2c2+1) -> one u32 per pair
    const size_t rowbase = (size_t)b * HW * (DIMC / 2);
    const uint32_t colw = (uint32_t)(h * 32) / 2 + (uint32_t)(c2);  // word offset of dh pair
#pragma unroll
    for (int dhb = 0; dhb < 4; ++dhb) {
        float a0 = O[dhb][0] * inv0, a1 = O[dhb][1] * inv0;
        float a2 = O[dhb][2] * inv1, a3 = O[dhb][3] * inv1;
        uint32_t h0 = pack_bf16(a0, a1);
        uint32_t l0 = pack_bf16(a0 - __uint_as_float(h0 << 16),
                                a1 - __uint_as_float(h0 & 0xffff0000u));
        uint32_t h1 = pack_bf16(a2, a3);
        uint32_t l1 = pack_bf16(a2 - __uint_as_float(h1 << 16),
                                a3 - __uint_as_float(h1 & 0xffff0000u));
        size_t i0 = rowbase + (size_t)(m0 + mrow + r) * 128 + colw + dhb * 4;
        size_t i1 = rowbase + (size_t)(m0 + mrow + r + 8) * 128 + colw + dhb * 4;
        aothi[i0] = h0; aotlo[i0] = l0;
        aothi[i1] = h1; aotlo[i1] = l1;
    }
}

// ==================== launch ====================
extern "C" void kernel_launch(void* const* d_in, const int* in_sizes, int n_in,
                              void* d_out, int out_size)
{
    (void)in_sizes; (void)n_in; (void)out_size;
    const float* x    = (const float*)d_in[0];
    const float* kv   = (const float*)d_in[1];
    const float* wq   = (const float*)d_in[2];
    const float* bq   = (const float*)d_in[3];
    const float* wk   = (const float*)d_in[4];
    const float* bk   = (const float*)d_in[5];
    const float* wv   = (const float*)d_in[6];
    const float* bv   = (const float*)d_in[7];
    const float* wdw  = (const float*)d_in[8];
    const float* bdw  = (const float*)d_in[9];
    const float* lnw  = (const float*)d_in[10];
    const float* lnb  = (const float*)d_in[11];
    const float* woff = (const float*)d_in[12];
    const float* wo   = (const float*)d_in[13];
    const float* bo   = (const float*)d_in[14];
    float* out = (float*)d_out;

    float *q, *kvs;
    __nv_bfloat16 *kthi, *ktlo, *vhi, *vlo;
    __nv_bfloat16 *wqhi, *wqlo, *wohi, *wolo, *xthi, *xtlo, *aothi, *aotlo;
    cudaGetSymbolAddress((void**)&q,     g_q);
    cudaGetSymbolAddress((void**)&kvs,   g_kvs);
    cudaGetSymbolAddress((void**)&kthi,  g_kthi);
    cudaGetSymbolAddress((void**)&ktlo,  g_ktlo);
    cudaGetSymbolAddress((void**)&vhi,   g_vhi);
    cudaGetSymbolAddress((void**)&vlo,   g_vlo);
    cudaGetSymbolAddress((void**)&wqhi,  g_wqhi);
    cudaGetSymbolAddress((void**)&wqlo,  g_wqlo);
    cudaGetSymbolAddress((void**)&wohi,  g_wohi);
    cudaGetSymbolAddress((void**)&wolo,  g_wolo);
    cudaGetSymbolAddress((void**)&xthi,  g_xthi);
    cudaGetSymbolAddress((void**)&xtlo,  g_xtlo);
    cudaGetSymbolAddress((void**)&aothi, g_aothi);
    cudaGetSymbolAddress((void**)&aotlo, g_aotlo);

    cudaFuncSetAttribute(attn_mma_kernel, cudaFuncAttributeMaxDynamicSharedMemorySize, A_SMEM);
    cudaFuncSetAttribute(gemm_tc_kernel,  cudaFuncAttributeMaxDynamicSharedMemorySize, G_SMEM);

    // 0) weight split + x transpose/split
    split_w_kernel<<<256, 512>>>(wq, wo, wqhi, wqlo, wohi, wolo);
    split_x_kernel<<<dim3(HW / 32, DIMC / 32, BATCH), 256>>>(x, xthi, xtlo);
    // 1) q projection (tensor-core)
    gemm_tc_kernel<<<dim3(HW / 64, 2, BATCH), 256, G_SMEM>>>(
        (const uint32_t*)wqhi, (const uint32_t*)wqlo, bq,
        (const uint32_t*)xthi, (const uint32_t*)xtlo, q);
    // 2) depthwise + LN + GELU + offsets + bilinear sample
    offset_sample_kernel<<<(64 * NKS) / 8, 256>>>(q, kv, wdw, bdw, lnw, lnb, woff, kvs);
    // 3) fused k+v projections (fp32 core, split epilogue)
    gemm_kv_kernel<<<dim3(NKS / 64, 8, BATCH), 256>>>(wk, bk, wv, bv, kvs, kthi, ktlo, vhi, vlo);
    // 4) attention -> split transposed output
    attn_mma_kernel<<<dim3(HW / 128, 64), 256, A_SMEM>>>(
        q, (const uint32_t*)kthi, (const uint32_t*)ktlo,
        (const uint32_t*)vhi, (const uint32_t*)vlo,
        (uint32_t*)aothi, (uint32_t*)aotlo);
    // 5) output projection (tensor-core)
    gemm_tc_kernel<<<dim3(HW / 64, 2, BATCH), 256, G_SMEM>>>(
        (const uint32_t*)wohi, (const uint32_t*)wolo, bo,
        (const uint32_t*)aothi, (const uint32_t*)aotlo, out);
}

// round 8
// speedup vs baseline: 3.1281x; 1.3145x over previous
#include <cuda_runtime.h>
#include <cuda_bf16.h>
#include <math.h>
#include <stdint.h>

#define BATCH 8
#define DIMC  256
#define HH    48
#define WWD   48
#define HW    2304
#define HEADS 8
#define DH    32
#define HKD   24
#define NKS   576
#define ATTN_SCALE 0.17677669529663687f

// ==================== scratch (device globals) ====================
__device__ float g_q   [BATCH * DIMC * HW];
__device__ float g_kvT [64 * HW * DH];          // [bh][hw][dh]
__device__ float g_kvsT[BATCH * NKS * DIMC];    // [b][pos][ch]
__device__ __nv_bfloat16 g_kthi[64 * NKS * DH];
__device__ __nv_bfloat16 g_ktlo[64 * NKS * DH];
__device__ __nv_bfloat16 g_vhi [64 * DH * NKS];
__device__ __nv_bfloat16 g_vlo [64 * DH * NKS];
__device__ __nv_bfloat16 g_wqhi[DIMC * DIMC], g_wqlo[DIMC * DIMC];
__device__ __nv_bfloat16 g_wohi[DIMC * DIMC], g_wolo[DIMC * DIMC];
__device__ __nv_bfloat16 g_xthi[BATCH * HW * DIMC], g_xtlo[BATCH * HW * DIMC];
__device__ __nv_bfloat16 g_aothi[BATCH * HW * DIMC], g_aotlo[BATCH * HW * DIMC];

// ==================== helpers ====================
__device__ __forceinline__ float warp_sum(float v) {
#pragma unroll
    for (int o = 16; o; o >>= 1) v += __shfl_xor_sync(0xffffffffu, v, o);
    return v;
}
__device__ __forceinline__ uint32_t smem_u32(const void* p) {
    uint32_t a;
    asm("{ .reg .u64 t; cvta.to.shared.u64 t, %1; cvt.u32.u64 %0, t; }" : "=r"(a) : "l"(p));
    return a;
}
__device__ __forceinline__ uint32_t pack_bf16(float a, float b) {
    uint32_t r;
    asm("cvt.rn.satfinite.bf16x2.f32 %0, %1, %2;" : "=r"(r) : "f"(b), "f"(a));
    return r;
}
__device__ __forceinline__ void mma16816(float* d, const uint32_t* a, const uint32_t* b,
                                         const float* c) {
    asm volatile("mma.sync.aligned.m16n8k16.row.col.f32.bf16.bf16.f32 "
        "{%0,%1,%2,%3}, {%4,%5,%6,%7}, {%8,%9}, {%10,%11,%12,%13};"
        : "=f"(d[0]), "=f"(d[1]), "=f"(d[2]), "=f"(d[3])
        : "r"(a[0]), "r"(a[1]), "r"(a[2]), "r"(a[3]),
          "r"(b[0]), "r"(b[1]),
          "f"(c[0]), "f"(c[1]), "f"(c[2]), "f"(c[3]));
}
__device__ __forceinline__ void ldsm_x4(uint32_t& r0, uint32_t& r1, uint32_t& r2,
                                        uint32_t& r3, uint32_t addr) {
    asm volatile("ldmatrix.sync.aligned.m8n8.x4.shared.b16 {%0,%1,%2,%3}, [%4];"
                 : "=r"(r0), "=r"(r1), "=r"(r2), "=r"(r3) : "r"(addr));
}
__device__ __forceinline__ void cp16(uint32_t saddr, const void* g) {
    asm volatile("cp.async.cg.shared.global [%0], [%1], 16;" :: "r"(saddr), "l"(g));
}
#define CP_COMMIT() asm volatile("cp.async.commit_group;" ::: "memory")
#define CP_WAIT1()  asm volatile("cp.async.wait_group 1;" ::: "memory")
#define CP_WAIT0()  asm volatile("cp.async.wait_group 0;" ::: "memory")

// ==================== weight split ====================
__global__ void split_w_kernel(const float* __restrict__ wq, const float* __restrict__ wo,
                               __nv_bfloat16* __restrict__ wqhi, __nv_bfloat16* __restrict__ wqlo,
                               __nv_bfloat16* __restrict__ wohi, __nv_bfloat16* __restrict__ wolo)
{
    int i = blockIdx.x * 512 + threadIdx.x;
    float x;
    __nv_bfloat16 hi;
    if (i < 65536) {
        x = wq[i]; hi = __float2bfloat16(x);
        wqhi[i] = hi; wqlo[i] = __float2bfloat16(x - __bfloat162float(hi));
    } else {
        int j = i - 65536;
        x = wo[j]; hi = __float2bfloat16(x);
        wohi[j] = hi; wolo[j] = __float2bfloat16(x - __bfloat162float(hi));
    }
}

// ==================== x transpose + split ====================
__global__ void split_x_kernel(const float* __restrict__ x,
                               __nv_bfloat16* __restrict__ xthi,
                               __nv_bfloat16* __restrict__ xtlo)
{
    __shared__ float tile[32][33];
    const int n0 = blockIdx.x * 32, c0 = blockIdx.y * 32, b = blockIdx.z;
    const int tid = threadIdx.x;
    for (int i = tid; i < 1024; i += 256) {
        int c = i >> 5, n = i & 31;
        tile[c][n] = x[((size_t)b * DIMC + c0 + c) * HW + n0 + n];
    }
    __syncthreads();
    for (int i = tid; i < 1024; i += 256) {
        int n = i >> 5, c = i & 31;
        float v = tile[c][n];
        __nv_bfloat16 hi = __float2bfloat16(v);
        size_t idx = ((size_t)b * HW + n0 + n) * DIMC + c0 + c;
        xthi[idx] = hi;
        xtlo[idx] = __float2bfloat16(v - __bfloat162float(hi));
    }
}

// ==================== kv transpose: kv[b][ch][hw] -> kvT[bh][hw][dh] ====================
__global__ void transpose_kv_kernel(const float* __restrict__ kv, float* __restrict__ kvT)
{
    __shared__ float tile[32][33];
    const int n0 = blockIdx.x * 32;          // hw tile
    const int h  = blockIdx.y;               // head
    const int b  = blockIdx.z;
    const int tid = threadIdx.x;
    for (int i = tid; i < 1024; i += 256) {
        int c = i >> 5, n = i & 31;
        tile[c][n] = kv[((size_t)b * DIMC + h * DH + c) * HW + n0 + n];
    }
    __syncthreads();
    for (int i = tid; i < 1024; i += 256) {
        int n = i >> 5, c = i & 31;
        kvT[(((size_t)(b * 8 + h)) * HW + n0 + n) * DH + c] = tile[c][n];
    }
}

// ==================== tensor-core projection GEMM ====================
#define G_BUF  30720
#define G_SMEM 61440

__global__ void __launch_bounds__(256)
gemm_tc_kernel(const uint32_t* __restrict__ whi, const uint32_t* __restrict__ wlo,
               const float* __restrict__ bias,
               const uint32_t* __restrict__ xthi, const uint32_t* __restrict__ xtlo,
               float* __restrict__ C)
{
    extern __shared__ char smem[];
    const uint32_t sb = smem_u32(smem);
    const int tid = threadIdx.x;
    const int lane = tid & 31, warp = tid >> 5;
    const int n0 = blockIdx.x * 64;
    const int m0 = blockIdx.y * 128;
    const int b  = blockIdx.z;

    const uint32_t* xh = xthi + (size_t)b * HW * (DIMC / 2);
    const uint32_t* xl = xtlo + (size_t)b * HW * (DIMC / 2);

    auto prefetch = [&](int kc, int buf) {
        const uint32_t bb = sb + buf * G_BUF;
#pragma unroll
        for (int s = tid; s < 1536; s += 256) {
            if (s < 512) {
                int row = s >> 2, p = s & 3;
                cp16(bb + row * 80 + p * 16, whi + (size_t)(m0 + row) * 128 + kc * 16 + p * 4);
            } else if (s < 1024) {
                int t = s - 512, row = t >> 2, p = t & 3;
                cp16(bb + 10240 + row * 80 + p * 16, wlo + (size_t)(m0 + row) * 128 + kc * 16 + p * 4);
            } else if (s < 1280) {
                int t = s - 1024, row = t >> 2, p = t & 3;
                cp16(bb + 20480 + row * 80 + p * 16, xh + (size_t)(n0 + row) * 128 + kc * 16 + p * 4);
            } else {
                int t = s - 1280, row = t >> 2, p = t & 3;
                cp16(bb + 25600 + row * 80 + p * 16, xl + (size_t)(n0 + row) * 128 + kc * 16 + p * 4);
            }
        }
        CP_COMMIT();
    };

    prefetch(0, 0);

    const int warp_m = warp >> 1, warp_n = warp & 1;
    const int m_base = warp_m * 32, n_base = warp_n * 32;
    const uint32_t a_laneoff = (uint32_t)((lane & 15) * 80 + (lane >> 4) * 16);
    const uint32_t b_laneoff = (uint32_t)((lane & 7) * 80 + (lane >> 3) * 16);

    float acc[2][4][4] = {};

    for (int kc = 0; kc < 8; ++kc) {
        if (kc < 7) { prefetch(kc + 1, (kc + 1) & 1); CP_WAIT1(); }
        else        { CP_WAIT0(); }
        __syncthreads();
        const uint32_t bb = sb + (kc & 1) * G_BUF;

        uint32_t bfh[4][4], bfl[4][4];
#pragma unroll
        for (int nf = 0; nf < 4; ++nf) {
            uint32_t ad = bb + 20480u + (uint32_t)(n_base + nf * 8) * 80u + b_laneoff;
            ldsm_x4(bfh[nf][0], bfh[nf][1], bfh[nf][2], bfh[nf][3], ad);
            ldsm_x4(bfl[nf][0], bfl[nf][1], bfl[nf][2], bfl[nf][3], ad + 5120u);
        }
#pragma unroll
        for (int ks = 0; ks < 2; ++ks) {
#pragma unroll
            for (int mf = 0; mf < 2; ++mf) {
                uint32_t ad = bb + (uint32_t)(m_base + mf * 16) * 80u + a_laneoff + (uint32_t)ks * 32u;
                uint32_t ah[4], al[4];
                ldsm_x4(ah[0], ah[1], ah[2], ah[3], ad);
                ldsm_x4(al[0], al[1], al[2], al[3], ad + 10240u);
#pragma unroll
                for (int nf = 0; nf < 4; ++nf) {
                    uint32_t bh2[2] = { bfh[nf][ks * 2], bfh[nf][ks * 2 + 1] };
                    uint32_t bl2[2] = { bfl[nf][ks * 2], bfl[nf][ks * 2 + 1] };
                    mma16816(acc[mf][nf], ah, bh2, acc[mf][nf]);
                    mma16816(acc[mf][nf], ah, bl2, acc[mf][nf]);
                    mma16816(acc[mf][nf], al, bh2, acc[mf][nf]);
                }
            }
        }
        __syncthreads();
    }

    const int r = lane >> 2, c2 = lane & 3;
    float* Cb = C + (size_t)b * DIMC * HW;
#pragma unroll
    for (int mf = 0; mf < 2; ++mf) {
        int mrow = m0 + m_base + mf * 16;
        float b0 = bias[mrow + r], b1 = bias[mrow + r + 8];
#pragma unroll
        for (int nf = 0; nf < 4; ++nf) {
            int n = n0 + n_base + nf * 8 + c2 * 2;
            *(float2*)(Cb + (size_t)(mrow + r) * HW + n) =
                make_float2(acc[mf][nf][0] + b0, acc[mf][nf][1] + b0);
            *(float2*)(Cb + (size_t)(mrow + r + 8) * HW + n) =
                make_float2(acc[mf][nf][2] + b1, acc[mf][nf][3] + b1);
        }
    }
}

// ==================== fused k+v GEMM (fp32 core), X = kvsT[b][n][k] ====================
__global__ void gemm_kv_kernel(const float* __restrict__ Wk, const float* __restrict__ bk,
                               const float* __restrict__ Wv, const float* __restrict__ bv,
                               const float* __restrict__ X,
                               __nv_bfloat16* __restrict__ kthi, __nv_bfloat16* __restrict__ ktlo,
                               __nv_bfloat16* __restrict__ vhi,  __nv_bfloat16* __restrict__ vlo)
{
    __shared__ float As[16][64];
    __shared__ float Bs[16][64];
    const int n0 = blockIdx.x * 64;
    const bool isV = blockIdx.y >= 4;
    const int m0 = (blockIdx.y & 3) * 64;
    const float* W  = isV ? Wv : Wk;
    const float* bb = isV ? bv : bk;
    X += (size_t)blockIdx.z * NKS * DIMC;
    const int tid = threadIdx.x;
    const int tx = tid & 15, ty = tid >> 4;
    float acc[4][4] = {};
    for (int k0 = 0; k0 < DIMC; k0 += 16) {
        {
            int mm = tid >> 2, kq = tid & 3;
            float4 a = *(const float4*)(W + (size_t)(m0 + mm) * DIMC + k0 + kq * 4);
            As[kq * 4 + 0][mm] = a.x; As[kq * 4 + 1][mm] = a.y;
            As[kq * 4 + 2][mm] = a.z; As[kq * 4 + 3][mm] = a.w;
        }
        {
            int nn = tid >> 2, kq = tid & 3;
            float4 v = *(const float4*)(X + (size_t)(n0 + nn) * DIMC + k0 + kq * 4);
            Bs[kq * 4 + 0][nn] = v.x; Bs[kq * 4 + 1][nn] = v.y;
            Bs[kq * 4 + 2][nn] = v.z; Bs[kq * 4 + 3][nn] = v.w;
        }
        __syncthreads();
#pragma unroll
        for (int kk = 0; kk < 16; ++kk) {
            float4 a = *(const float4*)(&As[kk][ty * 4]);
            float4 b = *(const float4*)(&Bs[kk][tx * 4]);
            float av[4] = {a.x, a.y, a.z, a.w};
            float bv2[4] = {b.x, b.y, b.z, b.w};
#pragma unroll
            for (int i = 0; i < 4; ++i)
#pragma unroll
                for (int j = 0; j < 4; ++j) acc[i][j] += av[i] * bv2[j];
        }
        __syncthreads();
    }
    const int mbase = m0 + ty * 4;
    const int h  = mbase >> 5;
    const int dh0 = mbase & 31;
    const int bh = blockIdx.z * 8 + h;
    float hi4[4][4], lo4[4][4];
#pragma unroll
    for (int i = 0; i < 4; ++i) {
        float bi = bb[mbase + i];
#pragma unroll
        for (int j = 0; j < 4; ++j) {
            float x = acc[i][j] + bi;
            float hv = __bfloat162float(__float2bfloat16(x));
            hi4[i][j] = hv;
            lo4[i][j] = x - hv;
        }
    }
    if (!isV) {
        __nv_bfloat16* oh = kthi + (size_t)bh * NKS * DH;
        __nv_bfloat16* ol = ktlo + (size_t)bh * NKS * DH;
#pragma unroll
        for (int j = 0; j < 4; ++j) {
            int n = n0 + tx * 4 + j;
            *(uint2*)(oh + (size_t)n * DH + dh0) =
                make_uint2(pack_bf16(hi4[0][j], hi4[1][j]), pack_bf16(hi4[2][j], hi4[3][j]));
            *(uint2*)(ol + (size_t)n * DH + dh0) =
                make_uint2(pack_bf16(lo4[0][j], lo4[1][j]), pack_bf16(lo4[2][j], lo4[3][j]));
        }
    } else {
        __nv_bfloat16* oh = vhi + (size_t)bh * DH * NKS;
        __nv_bfloat16* ol = vlo + (size_t)bh * DH * NKS;
#pragma unroll
        for (int i = 0; i < 4; ++i) {
            int n = n0 + tx * 4;
            *(uint2*)(oh + (size_t)(dh0 + i) * NKS + n) =
                make_uint2(pack_bf16(hi4[i][0], hi4[i][1]), pack_bf16(hi4[i][2], hi4[i][3]));
            *(uint2*)(ol + (size_t)(dh0 + i) * NKS + n) =
                make_uint2(pack_bf16(lo4[i][0], lo4[i][1]), pack_bf16(lo4[i][2], lo4[i][3]));
        }
    }
}

// ==================== offset + sample (smem conv patch + coalesced gathers) ====================
// grid (6, 64): blockIdx.x = 4-row tile, blockIdx.y = bh. 256 threads = 8 warps.
// smem patch: q rows [2*hk0-2, 2*hk0+8] x 48 x 32dh, layout s[pos][dh] stride 33.
#define OS_SMEM (528 * 33 * 4)

__global__ void __launch_bounds__(256)
offset_sample_kernel(const float* __restrict__ q,
                     const float* __restrict__ kvT,
                     const float* __restrict__ w_dw,
                     const float* __restrict__ b_dw,
                     const float* __restrict__ ln_w,
                     const float* __restrict__ ln_b,
                     const float* __restrict__ w_off,
                     float* __restrict__ kvsT)
{
    extern __shared__ float sp[];           // [528][33]
    __shared__ float s_wdw[32 * 25];
    __shared__ float s_bdw[32], s_lnw[32], s_lnb[32], s_woff[64];

    const int tid = threadIdx.x;
    const int bh = blockIdx.y, b = bh >> 3, h = bh & 7;
    const int hk0 = blockIdx.x * 4;
    const int y0 = 2 * hk0 - 2;

    for (int i = tid; i < 800; i += 256) s_wdw[i] = w_dw[i];
    if (tid < 32) { s_bdw[tid] = b_dw[tid]; s_lnw[tid] = ln_w[tid]; s_lnb[tid] = ln_b[tid]; }
    if (tid < 64) s_woff[tid] = w_off[tid];

    // load q patch: 32 dh x 11 rows x 48 cols, coalesced; zero OOB rows
    const float* qh = q + (size_t)(b * DIMC + h * DH) * HW;
    for (int i = tid; i < 16896; i += 256) {
        int dh = i / 528, p = i - dh * 528;
        int y = y0 + p / 48, x = p - (p / 48) * 48;
        float v = 0.f;
        if ((unsigned)y < (unsigned)HH)
            v = qh[(size_t)dh * HW + y * WWD + x];
        sp[p * 33 + dh] = v;
    }
    __syncthreads();

    const int lane = tid & 31, warp = tid >> 5;
    const float* kvb = kvT + (size_t)bh * HW * DH;
    float* outb = kvsT + ((size_t)b * NKS) * DIMC + h * DH;

#pragma unroll
    for (int s = 0; s < 12; ++s) {
        const int p = s * 8 + warp;          // 0..95 within tile
        const int hk = hk0 + p / 24;
        const int wk = p - (p / 24) * 24;
        const int pos = hk * HKD + wk;

        // depthwise 5x5 s2 from smem patch
        const int dy = 2 * (hk - hk0);
        float t = 0.f;
#pragma unroll
        for (int i = 0; i < 5; ++i) {
            const int rb = (dy + i) * 48;
#pragma unroll
            for (int j = 0; j < 5; ++j) {
                int xx = wk * 2 - 2 + j;
                if ((unsigned)xx < (unsigned)WWD)
                    t += sp[(rb + xx) * 33 + lane] * s_wdw[lane * 25 + i * 5 + j];
            }
        }
        t += s_bdw[lane];

        // LayerNorm over 32 channels
        float mu  = warp_sum(t) * (1.f / 32.f);
        float d   = t - mu;
        float var = warp_sum(d * d) * (1.f / 32.f);
        t = d * rsqrtf(var + 1e-5f) * s_lnw[lane] + s_lnb[lane];
        t = 0.5f * t * (1.f + erff(t * 0.70710678118654752f));

        float o0 = warp_sum(s_woff[lane] * t);
        float o1 = warp_sum(s_woff[32 + lane] * t);

        const float refy = (0.5f + (float)hk) * (2.f / 23.f) - 1.f;
        const float refx = (0.5f + (float)wk) * (2.f / 23.f) - 1.f;
        float py = fminf(fmaxf(o0 + refy, -1.f), 1.f);
        float px = fminf(fmaxf(o1 + refx, -1.f), 1.f);

        float gx = (px + 1.f) * 0.5f * 47.f;
        float gy = (py + 1.f) * 0.5f * 47.f;
        float fx = floorf(gx), fy = floorf(gy);
        float wx = gx - fx,   wy = gy - fy;
        int x0i = min(max((int)fx, 0), 47);
        int x1i = min(max((int)fx + 1, 0), 47);
        int y0i = min(max((int)fy, 0), 47);
        int y1i = min(max((int)fy + 1, 0), 47);

        // coalesced bilinear: each tap = one 128B line
        float v00 = kvb[(size_t)(y0i * WWD + x0i) * DH + lane];
        float v01 = kvb[(size_t)(y0i * WWD + x1i) * DH + lane];
        float v10 = kvb[(size_t)(y1i * WWD + x0i) * DH + lane];
        float v11 = kvb[(size_t)(y1i * WWD + x1i) * DH + lane];

        float val = (1.f - wx) * (1.f - wy) * v00 + wx * (1.f - wy) * v01 +
                    (1.f - wx) * wy * v10 + wx * wy * v11;

        outb[(size_t)pos * DIMC + lane] = val;   // coalesced store
    }
}

// ==================== streamed mma.sync attention ====================
#define BUF_SZ  19456
#define A_QSTG  38912
#define A_SMEM  59392

__global__ void __launch_bounds__(256)
attn_mma_kernel(const float* __restrict__ q,
                const uint32_t* __restrict__ kthi, const uint32_t* __restrict__ ktlo,
                const uint32_t* __restrict__ vhi,  const uint32_t* __restrict__ vlo,
                uint32_t* __restrict__ aothi, uint32_t* __restrict__ aotlo)
{
    extern __shared__ char smem[];
    const uint32_t sb = smem_u32(smem);
    __nv_bfloat16* sqh = (__nv_bfloat16*)(smem + A_QSTG);
    __nv_bfloat16* sql = (__nv_bfloat16*)(smem + A_QSTG + 10240);

    const int tid  = threadIdx.x;
    const int lane = tid & 31, warp = tid >> 5;
    const int bh = blockIdx.y, b = bh >> 3, h = bh & 7;
    const int m0 = blockIdx.x * 128;

    const uint32_t* gkh = kthi + (size_t)bh * 9216;
    const uint32_t* gkl = ktlo + (size_t)bh * 9216;
    const uint32_t* gvh = vhi + (size_t)bh * 9216;
    const uint32_t* gvl = vlo + (size_t)bh * 9216;

    auto prefetch = [&](int c, int buf) {
        const uint32_t bb = sb + buf * BUF_SZ;
#pragma unroll
        for (int s = tid; s < 1024; s += 256) {
            if (s < 256) {
                int n = s >> 2, p = s & 3;
                cp16(bb + n * 80 + p * 16, gkh + c * 1024 + s * 4);
            } else if (s < 512) {
                int t = s - 256, n = t >> 2, p = t & 3;
                cp16(bb + 5120 + n * 80 + p * 16, gkl + c * 1024 + t * 4);
            } else if (s < 768) {
                int t = s - 512, dh = t >> 3, p = t & 7;
                cp16(bb + 10240 + dh * 144 + p * 16, gvh + dh * 288 + c * 32 + p * 4);
            } else {
                int t = s - 768, dh = t >> 3, p = t & 7;
                cp16(bb + 14848 + dh * 144 + p * 16, gvl + dh * 288 + c * 32 + p * 4);
            }
        }
        CP_COMMIT();
    };

    prefetch(0, 0);

    const float* qb = q + (size_t)(b * DIMC + h * DH) * HW + m0;
    for (int i = tid; i < 4096; i += 256) {
        int dh = i >> 7, m = i & 127;
        float x = qb[(size_t)dh * HW + m];
        __nv_bfloat16 hi = __float2bfloat16(x);
        float lo = x - __bfloat162float(hi);
        sqh[m * 40 + dh] = hi;
        sql[m * 40 + dh] = __float2bfloat16(lo);
    }
    __syncthreads();

    const int r = lane >> 2, c2 = lane & 3;
    const int mrow = warp * 16;
    uint32_t qfh[2][4], qfl[2][4];
#pragma unroll
    for (int ks = 0; ks < 2; ++ks) {
        int k0 = ks * 16 + c2 * 2;
        qfh[ks][0] = *(const uint32_t*)(sqh + (mrow + r) * 40 + k0);
        qfh[ks][1] = *(const uint32_t*)(sqh + (mrow + r + 8) * 40 + k0);
        qfh[ks][2] = *(const uint32_t*)(sqh + (mrow + r) * 40 + k0 + 8);
        qfh[ks][3] = *(const uint32_t*)(sqh + (mrow + r + 8) * 40 + k0 + 8);
        qfl[ks][0] = *(const uint32_t*)(sql + (mrow + r) * 40 + k0);
        qfl[ks][1] = *(const uint32_t*)(sql + (mrow + r + 8) * 40 + k0);
        qfl[ks][2] = *(const uint32_t*)(sql + (mrow + r) * 40 + k0 + 8);
        qfl[ks][3] = *(const uint32_t*)(sql + (mrow + r + 8) * 40 + k0 + 8);
    }

    const uint32_t k_laneoff = ((uint32_t)(lane & 7) * 20u + (uint32_t)(lane >> 3) * 4u) * 4u;
    const uint32_t v_laneoff = ((uint32_t)(lane & 7) * 36u + (uint32_t)((lane >> 3) & 1) * 4u) * 4u;
    const uint32_t v_hl = (lane < 16) ? 10240u : 14848u;

    float O[4][4] = {};
    float rs0 = 0.f, rs1 = 0.f;

    for (int chunk = 0; chunk < 9; ++chunk) {
        if (chunk < 8) { prefetch(chunk + 1, (chunk + 1) & 1); CP_WAIT1(); }
        else           { CP_WAIT0(); }
        __syncthreads();

        const uint32_t bufb = sb + (chunk & 1) * BUF_SZ;
        float S[8][4];
#pragma unroll
        for (int nb = 0; nb < 8; ++nb)
#pragma unroll
            for (int i = 0; i < 4; ++i) S[nb][i] = 0.f;

#pragma unroll
        for (int nb = 0; nb < 8; ++nb) {
            uint32_t h0, h1, h2, h3, l0, l1, l2, l3;
            ldsm_x4(h0, h1, h2, h3, bufb + k_laneoff + (uint32_t)nb * 640u);
            ldsm_x4(l0, l1, l2, l3, bufb + 5120u + k_laneoff + (uint32_t)nb * 640u);
            uint32_t bh0[2] = {h0, h1}, bh1[2] = {h2, h3};
            uint32_t bl0[2] = {l0, l1}, bl1[2] = {l2, l3};
            mma16816(S[nb], qfh[0], bh0, S[nb]);
            mma16816(S[nb], qfh[1], bh1, S[nb]);
            mma16816(S[nb], qfh[0], bl0, S[nb]);
            mma16816(S[nb], qfh[1], bl1, S[nb]);
            mma16816(S[nb], qfl[0], bh0, S[nb]);
            mma16816(S[nb], qfl[1], bh1, S[nb]);
        }

#pragma unroll
        for (int j = 0; j < 4; ++j) {
            float e[8];
#pragma unroll
            for (int i = 0; i < 4; ++i) {
                e[i]     = __expf(S[2 * j][i]     * ATTN_SCALE);
                e[4 + i] = __expf(S[2 * j + 1][i] * ATTN_SCALE);
            }
            rs0 += e[0] + e[1] + e[4] + e[5];
            rs1 += e[2] + e[3] + e[6] + e[7];

            uint32_t ph[4], pl[4];
#pragma unroll
            for (int i = 0; i < 4; ++i) {
                float a = e[2 * i], bb2 = e[2 * i + 1];
                uint32_t hp = pack_bf16(a, bb2);
                float ra = a   - __uint_as_float(hp << 16);
                float rb = bb2 - __uint_as_float(hp & 0xffff0000u);
                ph[i] = hp;
                pl[i] = pack_bf16(ra, rb);
            }

#pragma unroll
            for (int dhb = 0; dhb < 4; ++dhb) {
                uint32_t m0r, m1r, m2r, m3r;
                ldsm_x4(m0r, m1r, m2r, m3r,
                        bufb + v_hl + v_laneoff + (uint32_t)dhb * 1152u + (uint32_t)j * 32u);
                uint32_t bh2[2] = {m0r, m1r}, bl2[2] = {m2r, m3r};
                mma16816(O[dhb], ph, bh2, O[dhb]);
                mma16816(O[dhb], ph, bl2, O[dhb]);
                mma16816(O[dhb], pl, bh2, O[dhb]);
            }
        }
        __syncthreads();
    }

    rs0 += __shfl_xor_sync(0xffffffffu, rs0, 1);
    rs0 += __shfl_xor_sync(0xffffffffu, rs0, 2);
    rs1 += __shfl_xor_sync(0xffffffffu, rs1, 1);
    rs1 += __shfl_xor_sync(0xffffffffu, rs1, 2);
    float inv0 = 1.f / rs0, inv1 = 1.f / rs1;

    const size_t rowbase = (size_t)b * HW * (DIMC / 2);
    const uint32_t colw = (uint32_t)(h * 32) / 2 + (uint32_t)(c2);
#pragma unroll
    for (int dhb = 0; dhb < 4; ++dhb) {
        float a0 = O[dhb][0] * inv0, a1 = O[dhb][1] * inv0;
        float a2 = O[dhb][2] * inv1, a3 = O[dhb][3] * inv1;
        uint32_t h0 = pack_bf16(a0, a1);
        uint32_t l0 = pack_bf16(a0 - __uint_as_float(h0 << 16),
                                a1 - __uint_as_float(h0 & 0xffff0000u));
        uint32_t h1 = pack_bf16(a2, a3);
        uint32_t l1 = pack_bf16(a2 - __uint_as_float(h1 << 16),
                                a3 - __uint_as_float(h1 & 0xffff0000u));
        size_t i0 = rowbase + (size_t)(m0 + mrow + r) * 128 + colw + dhb * 4;
        size_t i1 = rowbase + (size_t)(m0 + mrow + r + 8) * 128 + colw + dhb * 4;
        aothi[i0] = h0; aotlo[i0] = l0;
        aothi[i1] = h1; aotlo[i1] = l1;
    }
}

// ==================== launch ====================
extern "C" void kernel_launch(void* const* d_in, const int* in_sizes, int n_in,
                              void* d_out, int out_size)
{
    (void)in_sizes; (void)n_in; (void)out_size;
    const float* x    = (const float*)d_in[0];
    const float* kv   = (const float*)d_in[1];
    const float* wq   = (const float*)d_in[2];
    const float* bq   = (const float*)d_in[3];
    const float* wk   = (const float*)d_in[4];
    const float* bk   = (const float*)d_in[5];
    const float* wv   = (const float*)d_in[6];
    const float* bv   = (const float*)d_in[7];
    const float* wdw  = (const float*)d_in[8];
    const float* bdw  = (const float*)d_in[9];
    const float* lnw  = (const float*)d_in[10];
    const float* lnb  = (const float*)d_in[11];
    const float* woff = (const float*)d_in[12];
    const float* wo   = (const float*)d_in[13];
    const float* bo   = (const float*)d_in[14];
    float* out = (float*)d_out;

    float *q, *kvT, *kvsT;
    __nv_bfloat16 *kthi, *ktlo, *vhi, *vlo;
    __nv_bfloat16 *wqhi, *wqlo, *wohi, *wolo, *xthi, *xtlo, *aothi, *aotlo;
    cudaGetSymbolAddress((void**)&q,     g_q);
    cudaGetSymbolAddress((void**)&kvT,   g_kvT);
    cudaGetSymbolAddress((void**)&kvsT,  g_kvsT);
    cudaGetSymbolAddress((void**)&kthi,  g_kthi);
    cudaGetSymbolAddress((void**)&ktlo,  g_ktlo);
    cudaGetSymbolAddress((void**)&vhi,   g_vhi);
    cudaGetSymbolAddress((void**)&vlo,   g_vlo);
    cudaGetSymbolAddress((void**)&wqhi,  g_wqhi);
    cudaGetSymbolAddress((void**)&wqlo,  g_wqlo);
    cudaGetSymbolAddress((void**)&wohi,  g_wohi);
    cudaGetSymbolAddress((void**)&wolo,  g_wolo);
    cudaGetSymbolAddress((void**)&xthi,  g_xthi);
    cudaGetSymbolAddress((void**)&xtlo,  g_xtlo);
    cudaGetSymbolAddress((void**)&aothi, g_aothi);
    cudaGetSymbolAddress((void**)&aotlo, g_aotlo);

    cudaFuncSetAttribute(attn_mma_kernel, cudaFuncAttributeMaxDynamicSharedMemorySize, A_SMEM);
    cudaFuncSetAttribute(gemm_tc_kernel,  cudaFuncAttributeMaxDynamicSharedMemorySize, G_SMEM);
    cudaFuncSetAttribute(offset_sample_kernel, cudaFuncAttributeMaxDynamicSharedMemorySize, OS_SMEM);

    // 0) preprocessing: weight split, x transpose/split, kv transpose
    split_w_kernel<<<256, 512>>>(wq, wo, wqhi, wqlo, wohi, wolo);
    split_x_kernel<<<dim3(HW / 32, DIMC / 32, BATCH), 256>>>(x, xthi, xtlo);
    transpose_kv_kernel<<<dim3(HW / 32, HEADS, BATCH), 256>>>(kv, kvT);
    // 1) q projection (tensor-core)
    gemm_tc_kernel<<<dim3(HW / 64, 2, BATCH), 256, G_SMEM>>>(
        (const uint32_t*)wqhi, (const uint32_t*)wqlo, bq,
        (const uint32_t*)xthi, (const uint32_t*)xtlo, q);
    // 2) depthwise + LN + GELU + offsets + bilinear sample (coalesced)
    offset_sample_kernel<<<dim3(6, 64), 256, OS_SMEM>>>(q, kvT, wdw, bdw, lnw, lnb, woff, kvsT);
    // 3) fused k+v projections
    gemm_kv_kernel<<<dim3(NKS / 64, 8, BATCH), 256>>>(wk, bk, wv, bv, kvsT, kthi, ktlo, vhi, vlo);
    // 4) attention -> split transposed output
    attn_mma_kernel<<<dim3(HW / 128, 64), 256, A_SMEM>>>(
        q, (const uint32_t*)kthi, (const uint32_t*)ktlo,
        (const uint32_t*)vhi, (const uint32_t*)vlo,
        (uint32_t*)aothi, (uint32_t*)aotlo);
    // 5) output projection (tensor-core)
    gemm_tc_kernel<<<dim3(HW / 64, 2, BATCH), 256, G_SMEM>>>(
        (const uint32_t*)wohi, (const uint32_t*)wolo, bo,
        (const uint32_t*)aothi, (const uint32_t*)aotlo, out);
}